// round 1
// baseline (speedup 1.0000x reference)
#include <cuda_runtime.h>

#define BB 2
#define SS 3144
#define CC 256
#define HH 8
#define HD 32
#define QN 8
#define MTOT (BB*SS)            /* 6288 */
#define SCALE 0.1767766952966369f
#define NKT ((SS + 63) / 64)    /* 50 key tiles */

__device__ float d_q[BB*HH*SS*HD];   // head-major: ((b*H+h)*S + s)*HD + d
__device__ float d_k[BB*HH*SS*HD];   // pre-scaled by SCALE
__device__ float d_v[BB*SS*CC];      // (b,s,c)
__device__ float d_acc[BB*SS*CC];    // attention out (+lepe) before final proj

typedef unsigned long long u64;

__device__ __forceinline__ void fma2(u64 &d, u64 a, u64 b) {
    asm("fma.rn.f32x2 %0, %1, %2, %0;" : "+l"(d) : "l"(a), "l"(b));
}
__device__ __forceinline__ void add2(u64 &d, u64 a) {
    asm("add.rn.f32x2 %0, %1, %0;" : "+l"(d) : "l"(a));
}
__device__ __forceinline__ u64 pack2(float lo, float hi) {
    u64 r; asm("mov.b64 %0, {%1, %2};" : "=l"(r) : "f"(lo), "f"(hi)); return r;
}
__device__ __forceinline__ float2 unpack2(u64 v) {
    float2 r; asm("mov.b64 {%0, %1}, %2;" : "=f"(r.x), "=f"(r.y) : "l"(v)); return r;
}

// ---------------------------------------------------------------------------
// Kernel 1: fused QKV projection.  y = x @ [wq;wk;wv]^T + bias, M=6288, N=768, K=256
// ---------------------------------------------------------------------------
__global__ __launch_bounds__(256) void qkv_kernel(
    const float* __restrict__ x,
    const float* __restrict__ wq, const float* __restrict__ bq,
    const float* __restrict__ wk, const float* __restrict__ bk,
    const float* __restrict__ wv, const float* __restrict__ bv)
{
    __shared__ float Xs[64][36];
    __shared__ float Wt[64][36];
    int m0 = blockIdx.x * 64;
    int n0 = blockIdx.y * 64;
    int t = threadIdx.x;
    int ty = t >> 4, tx = t & 15;

    int sec = n0 >> 8;             // 0=q, 1=k, 2=v (64-tiles never straddle)
    const float* wsec = (sec == 0) ? wq : (sec == 1) ? wk : wv;
    const float* bsec = (sec == 0) ? bq : (sec == 1) ? bk : bv;
    int nbase = n0 & 255;

    u64 sacc[4][4];
    #pragma unroll
    for (int i = 0; i < 4; i++)
        #pragma unroll
        for (int j = 0; j < 4; j++) sacc[i][j] = 0ull;

    for (int kk = 0; kk < CC; kk += 32) {
        __syncthreads();
        for (int f = t; f < 64*32/4; f += 256) {
            int r = f >> 3, c4 = (f & 7) << 2;
            int gm = m0 + r;
            float4 v = make_float4(0.f, 0.f, 0.f, 0.f);
            if (gm < MTOT) v = *(const float4*)(x + (size_t)gm*CC + kk + c4);
            *(float4*)&Xs[r][c4] = v;
            *(float4*)&Wt[r][c4] = *(const float4*)(wsec + (size_t)(nbase + r)*CC + kk + c4);
        }
        __syncthreads();
        #pragma unroll
        for (int d = 0; d < 32; d += 4) {
            u64 xr[4][2], wr[4][2];
            #pragma unroll
            for (int i = 0; i < 4; i++) {
                ulonglong2 v2 = *(const ulonglong2*)&Xs[ty + 16*i][d];
                xr[i][0] = v2.x; xr[i][1] = v2.y;
            }
            #pragma unroll
            for (int j = 0; j < 4; j++) {
                ulonglong2 v2 = *(const ulonglong2*)&Wt[tx + 16*j][d];
                wr[j][0] = v2.x; wr[j][1] = v2.y;
            }
            #pragma unroll
            for (int i = 0; i < 4; i++)
                #pragma unroll
                for (int j = 0; j < 4; j++) {
                    fma2(sacc[i][j], xr[i][0], wr[j][0]);
                    fma2(sacc[i][j], xr[i][1], wr[j][1]);
                }
        }
    }
    #pragma unroll
    for (int i = 0; i < 4; i++) {
        int gm = m0 + ty + 16*i;
        if (gm >= MTOT) continue;
        int b = gm / SS, srow = gm % SS;
        #pragma unroll
        for (int j = 0; j < 4; j++) {
            int c = nbase + tx + 16*j;
            float2 sv = unpack2(sacc[i][j]);
            float val = sv.x + sv.y + bsec[c];
            if (sec == 0) {
                d_q[(((size_t)b*HH + (c >> 5))*SS + srow)*HD + (c & 31)] = val;
            } else if (sec == 1) {
                d_k[(((size_t)b*HH + (c >> 5))*SS + srow)*HD + (c & 31)] = val * SCALE;
            } else {
                d_v[(size_t)gm*CC + c] = val;
            }
        }
    }
}

// ---------------------------------------------------------------------------
// Kernel 2: single-pass masked attention.
// O[q,:] = sum_k (mask+1e-6)*exp(q.k) * k[:]  /  rowsum    (values == scaled K)
// Grid: (B*H, 50 query tiles of 64). 256 threads.
// ---------------------------------------------------------------------------
__global__ __launch_bounds__(256) void attn_kernel(const float* __restrict__ mask)
{
    __shared__ float Qs[64][36];
    __shared__ float Ks[64][36];
    __shared__ float Wsm[64][68];

    int bh = blockIdx.x;
    int b = bh >> 3;
    int h = bh & 7;
    int q0 = blockIdx.y * 64;
    int t = threadIdx.x;
    int ty = t >> 4, tx = t & 15;

    const float* qptr = d_q + (size_t)bh * SS * HD;
    const float* kptr = d_k + (size_t)bh * SS * HD;
    const float* mptr = mask + (size_t)b * SS * SS;

    // load Q tile (zero-pad tail rows)
    for (int f = t; f < 64*HD/4; f += 256) {
        int r = f >> 3, c4 = (f & 7) << 2;
        int gq = q0 + r;
        float4 v = make_float4(0.f, 0.f, 0.f, 0.f);
        if (gq < SS) v = *(const float4*)(qptr + (size_t)gq*HD + c4);
        *(float4*)&Qs[r][c4] = v;
    }

    // PV mapping: row pr, cols [pc0, pc0+8)
    int pr = t & 63, pg = t >> 6;
    int pc0 = pg * 8;
    u64 oacc[4] = {0ull, 0ull, 0ull, 0ull};
    u64 rs2 = 0ull;

    for (int kt = 0; kt < NKT; kt++) {
        int k0 = kt * 64;
        __syncthreads();   // prev PV done (and Q ready on first iter)
        for (int f = t; f < 64*HD/4; f += 256) {
            int r = f >> 3, c4 = (f & 7) << 2;
            int gk = k0 + r;
            float4 v = make_float4(0.f, 0.f, 0.f, 0.f);
            if (gk < SS) v = *(const float4*)(kptr + (size_t)gk*HD + c4);
            *(float4*)&Ks[r][c4] = v;
        }
        __syncthreads();

        // ---- QK: rows ty+16i, cols tx+16j, 4x4 micro-tile, f32x2 over d ----
        u64 sacc[4][4];
        #pragma unroll
        for (int i = 0; i < 4; i++)
            #pragma unroll
            for (int j = 0; j < 4; j++) sacc[i][j] = 0ull;
        #pragma unroll
        for (int d = 0; d < HD; d += 4) {
            u64 q2[4][2], k2[4][2];
            #pragma unroll
            for (int i = 0; i < 4; i++) {
                ulonglong2 v2 = *(const ulonglong2*)&Qs[ty + 16*i][d];
                q2[i][0] = v2.x; q2[i][1] = v2.y;
            }
            #pragma unroll
            for (int j = 0; j < 4; j++) {
                ulonglong2 v2 = *(const ulonglong2*)&Ks[tx + 16*j][d];
                k2[j][0] = v2.x; k2[j][1] = v2.y;
            }
            #pragma unroll
            for (int i = 0; i < 4; i++)
                #pragma unroll
                for (int j = 0; j < 4; j++) {
                    fma2(sacc[i][j], q2[i][0], k2[j][0]);
                    fma2(sacc[i][j], q2[i][1], k2[j][1]);
                }
        }
        // ---- w = (mask+1e-6)*exp(s), stage into Wsm ----
        #pragma unroll
        for (int i = 0; i < 4; i++) {
            int gq = q0 + ty + 16*i;
            #pragma unroll
            for (int j = 0; j < 4; j++) {
                int gk = k0 + tx + 16*j;
                float2 sv = unpack2(sacc[i][j]);
                float s = sv.x + sv.y;
                float w = 0.f;
                if (gq < SS && gk < SS) {
                    float m = __ldg(mptr + (size_t)gq * SS + gk);
                    w = (m + 1e-6f) * __expf(s);
                }
                Wsm[ty + 16*i][tx + 16*j] = w;
            }
        }
        __syncthreads();

        // ---- PV: O[pr][pc0..pc0+8) += sum_j W[pr][j] * K[j][:]; rowsum free ----
        #pragma unroll 4
        for (int j = 0; j < 64; j += 4) {
            ulonglong2 w4 = *(const ulonglong2*)&Wsm[pr][j];
            add2(rs2, w4.x); add2(rs2, w4.y);
            float2 wa = unpack2(w4.x), wb = unpack2(w4.y);
            float ws[4] = {wa.x, wa.y, wb.x, wb.y};
            #pragma unroll
            for (int jj = 0; jj < 4; jj++) {
                u64 w2 = pack2(ws[jj], ws[jj]);
                ulonglong2 ka = *(const ulonglong2*)&Ks[j + jj][pc0];
                ulonglong2 kb = *(const ulonglong2*)&Ks[j + jj][pc0 + 4];
                fma2(oacc[0], w2, ka.x); fma2(oacc[1], w2, ka.y);
                fma2(oacc[2], w2, kb.x); fma2(oacc[3], w2, kb.y);
            }
        }
    }

    int gq = q0 + pr;
    if (gq < SS) {
        float2 rv = unpack2(rs2);
        float inv = 1.0f / (rv.x + rv.y);
        float* out = d_acc + ((size_t)b*SS + gq)*CC + h*HD + pc0;
        #pragma unroll
        for (int u = 0; u < 4; u++) {
            float2 o = unpack2(oacc[u]);
            out[u*2 + 0] = o.x * inv;
            out[u*2 + 1] = o.y * inv;
        }
    }
}

// ---------------------------------------------------------------------------
// Kernel 3: LEPE depthwise 5x5 conv on v[:, QN:], accumulated into d_acc
// ---------------------------------------------------------------------------
__global__ __launch_bounds__(256) void lepe_kernel(
    const float* __restrict__ lw, const float* __restrict__ lb)
{
    int blk = blockIdx.x;              // 0..B*3136-1
    int b = blk / 3136, p = blk % 3136;
    int y = p / 56, x = p % 56;
    int c = threadIdx.x;
    float a = lb[c];
    #pragma unroll
    for (int ky = 0; ky < 5; ky++) {
        int iy = y + ky - 2;
        if (iy < 0 || iy >= 56) continue;
        #pragma unroll
        for (int kx = 0; kx < 5; kx++) {
            int ix = x + kx - 2;
            if (ix < 0 || ix >= 56) continue;
            a += d_v[((size_t)b*SS + QN + iy*56 + ix)*CC + c] * lw[(ky*5 + kx)*CC + c];
        }
    }
    d_acc[((size_t)b*SS + QN + p)*CC + c] += a;
}

// ---------------------------------------------------------------------------
// Kernel 4: output projection.  out = acc @ wo^T + bo, M=6288, N=256, K=256
// ---------------------------------------------------------------------------
__global__ __launch_bounds__(256) void out_kernel(
    const float* __restrict__ wo, const float* __restrict__ bo, float* __restrict__ out)
{
    __shared__ float Xs[64][36];
    __shared__ float Wt[64][36];
    int m0 = blockIdx.x * 64;
    int n0 = blockIdx.y * 64;
    int t = threadIdx.x;
    int ty = t >> 4, tx = t & 15;

    u64 sacc[4][4];
    #pragma unroll
    for (int i = 0; i < 4; i++)
        #pragma unroll
        for (int j = 0; j < 4; j++) sacc[i][j] = 0ull;

    for (int kk = 0; kk < CC; kk += 32) {
        __syncthreads();
        for (int f = t; f < 64*32/4; f += 256) {
            int r = f >> 3, c4 = (f & 7) << 2;
            int gm = m0 + r;
            float4 v = make_float4(0.f, 0.f, 0.f, 0.f);
            if (gm < MTOT) v = *(const float4*)(d_acc + (size_t)gm*CC + kk + c4);
            *(float4*)&Xs[r][c4] = v;
            *(float4*)&Wt[r][c4] = *(const float4*)(wo + (size_t)(n0 + r)*CC + kk + c4);
        }
        __syncthreads();
        #pragma unroll
        for (int d = 0; d < 32; d += 4) {
            u64 xr[4][2], wr[4][2];
            #pragma unroll
            for (int i = 0; i < 4; i++) {
                ulonglong2 v2 = *(const ulonglong2*)&Xs[ty + 16*i][d];
                xr[i][0] = v2.x; xr[i][1] = v2.y;
            }
            #pragma unroll
            for (int j = 0; j < 4; j++) {
                ulonglong2 v2 = *(const ulonglong2*)&Wt[tx + 16*j][d];
                wr[j][0] = v2.x; wr[j][1] = v2.y;
            }
            #pragma unroll
            for (int i = 0; i < 4; i++)
                #pragma unroll
                for (int j = 0; j < 4; j++) {
                    fma2(sacc[i][j], xr[i][0], wr[j][0]);
                    fma2(sacc[i][j], xr[i][1], wr[j][1]);
                }
        }
    }
    #pragma unroll
    for (int i = 0; i < 4; i++) {
        int gm = m0 + ty + 16*i;
        if (gm >= MTOT) continue;
        #pragma unroll
        for (int j = 0; j < 4; j++) {
            int n = n0 + tx + 16*j;
            float2 sv = unpack2(sacc[i][j]);
            out[(size_t)gm*CC + n] = sv.x + sv.y + bo[n];
        }
    }
}

// ---------------------------------------------------------------------------
extern "C" void kernel_launch(void* const* d_in, const int* in_sizes, int n_in,
                              void* d_out, int out_size) {
    const float* x    = (const float*)d_in[0];
    const float* mask = (const float*)d_in[1];
    const float* wq   = (const float*)d_in[2];
    const float* bq   = (const float*)d_in[3];
    const float* wk   = (const float*)d_in[4];
    const float* bk   = (const float*)d_in[5];
    const float* wv   = (const float*)d_in[6];
    const float* bv   = (const float*)d_in[7];
    const float* lw   = (const float*)d_in[8];
    const float* lb   = (const float*)d_in[9];
    const float* wo   = (const float*)d_in[10];
    const float* bo   = (const float*)d_in[11];
    float* out = (float*)d_out;

    dim3 g1(99, 12);
    qkv_kernel<<<g1, 256>>>(x, wq, bq, wk, bk, wv, bv);
    dim3 g2(BB*HH, NKT);
    attn_kernel<<<g2, 256>>>(mask);
    lepe_kernel<<<BB*3136, 256>>>(lw, lb);
    dim3 g4(99, 4);
    out_kernel<<<g4, 256>>>(wo, bo, out);
}

// round 3
// speedup vs baseline: 1.9323x; 1.9323x over previous
#include <cuda_runtime.h>
#include <cuda_bf16.h>
#include <cstdint>

#define BB 2
#define SS 3144
#define CC 256
#define HH 8
#define HD 32
#define QN 8
#define MTOT (BB*SS)            /* 6288 */
#define SCALE 0.1767766952966369f
#define NKT2 ((SS + 63) / 64)   /* 50 key tiles of 64 */
#define NQT ((SS + 127) / 128)  /* 25 query tiles of 128 */

__device__ float d_q[BB*HH*SS*HD];   // head-major: ((b*H+h)*S + s)*HD + d
__device__ float d_k[BB*HH*SS*HD];   // pre-scaled by SCALE (used as K and V)
__device__ float d_v[BB*SS*CC];      // (b,s,c)
__device__ float d_acc[BB*SS*CC];    // attention out (+lepe) before final proj

typedef unsigned long long u64;
typedef unsigned int u32;
typedef unsigned short u16;

// ---------------- f32x2 helpers (for the GEMM kernels) ----------------
__device__ __forceinline__ void fma2(u64 &d, u64 a, u64 b) {
    asm("fma.rn.f32x2 %0, %1, %2, %0;" : "+l"(d) : "l"(a), "l"(b));
}
__device__ __forceinline__ float2 unpack2(u64 v) {
    float2 r; asm("mov.b64 {%0, %1}, %2;" : "=f"(r.x), "=f"(r.y) : "l"(v)); return r;
}

// ---------------- bf16 / mma helpers ----------------
__device__ __forceinline__ u32 smem_u32(const void* p) {
    u32 a;
    asm("{ .reg .u64 t; cvta.to.shared.u64 t, %1; cvt.u32.u64 %0, t; }" : "=r"(a) : "l"(p));
    return a;
}
__device__ __forceinline__ u16 f2bf(float f) {
    u16 r; asm("cvt.rn.bf16.f32 %0, %1;" : "=h"(r) : "f"(f)); return r;
}
__device__ __forceinline__ float bf2f(u16 h) { return __uint_as_float(((u32)h) << 16); }
// returns hi<<16 | lo  (lo = first/even element in memory & fragment order)
__device__ __forceinline__ u32 pack_bf2(float lo, float hi) {
    u32 r; asm("cvt.rn.bf16x2.f32 %0, %1, %2;" : "=r"(r) : "f"(hi), "f"(lo)); return r;
}
__device__ __forceinline__ void ldx2(u32 &r0, u32 &r1, u32 saddr) {
    asm volatile("ldmatrix.sync.aligned.m8n8.x2.shared.b16 {%0,%1}, [%2];"
                 : "=r"(r0), "=r"(r1) : "r"(saddr));
}
__device__ __forceinline__ void ldx4(u32* r, u32 saddr) {
    asm volatile("ldmatrix.sync.aligned.m8n8.x4.shared.b16 {%0,%1,%2,%3}, [%4];"
                 : "=r"(r[0]), "=r"(r[1]), "=r"(r[2]), "=r"(r[3]) : "r"(saddr));
}
__device__ __forceinline__ void mma16816(float* c, const u32* a, u32 b0, u32 b1) {
    asm volatile("mma.sync.aligned.m16n8k16.row.col.f32.bf16.bf16.f32 "
                 "{%0,%1,%2,%3}, {%4,%5,%6,%7}, {%8,%9}, {%0,%1,%2,%3};"
                 : "+f"(c[0]), "+f"(c[1]), "+f"(c[2]), "+f"(c[3])
                 : "r"(a[0]), "r"(a[1]), "r"(a[2]), "r"(a[3]), "r"(b0), "r"(b1));
}

// ---------------------------------------------------------------------------
// Kernel 1: fused QKV projection (f32x2 tiles)
// ---------------------------------------------------------------------------
__global__ __launch_bounds__(256) void qkv_kernel(
    const float* __restrict__ x,
    const float* __restrict__ wq, const float* __restrict__ bq,
    const float* __restrict__ wk, const float* __restrict__ bk,
    const float* __restrict__ wv, const float* __restrict__ bv)
{
    __shared__ float Xs[64][36];
    __shared__ float Wt[64][36];
    int m0 = blockIdx.x * 64;
    int n0 = blockIdx.y * 64;
    int t = threadIdx.x;
    int ty = t >> 4, tx = t & 15;

    int sec = n0 >> 8;
    const float* wsec = (sec == 0) ? wq : (sec == 1) ? wk : wv;
    const float* bsec = (sec == 0) ? bq : (sec == 1) ? bk : bv;
    int nbase = n0 & 255;

    u64 sacc[4][4];
    #pragma unroll
    for (int i = 0; i < 4; i++)
        #pragma unroll
        for (int j = 0; j < 4; j++) sacc[i][j] = 0ull;

    for (int kk = 0; kk < CC; kk += 32) {
        __syncthreads();
        for (int f = t; f < 64*32/4; f += 256) {
            int r = f >> 3, c4 = (f & 7) << 2;
            int gm = m0 + r;
            float4 v = make_float4(0.f, 0.f, 0.f, 0.f);
            if (gm < MTOT) v = *(const float4*)(x + (size_t)gm*CC + kk + c4);
            *(float4*)&Xs[r][c4] = v;
            *(float4*)&Wt[r][c4] = *(const float4*)(wsec + (size_t)(nbase + r)*CC + kk + c4);
        }
        __syncthreads();
        #pragma unroll
        for (int d = 0; d < 32; d += 4) {
            u64 xr[4][2], wr[4][2];
            #pragma unroll
            for (int i = 0; i < 4; i++) {
                ulonglong2 v2 = *(const ulonglong2*)&Xs[ty + 16*i][d];
                xr[i][0] = v2.x; xr[i][1] = v2.y;
            }
            #pragma unroll
            for (int j = 0; j < 4; j++) {
                ulonglong2 v2 = *(const ulonglong2*)&Wt[tx + 16*j][d];
                wr[j][0] = v2.x; wr[j][1] = v2.y;
            }
            #pragma unroll
            for (int i = 0; i < 4; i++)
                #pragma unroll
                for (int j = 0; j < 4; j++) {
                    fma2(sacc[i][j], xr[i][0], wr[j][0]);
                    fma2(sacc[i][j], xr[i][1], wr[j][1]);
                }
        }
    }
    #pragma unroll
    for (int i = 0; i < 4; i++) {
        int gm = m0 + ty + 16*i;
        if (gm >= MTOT) continue;
        int b = gm / SS, srow = gm % SS;
        #pragma unroll
        for (int j = 0; j < 4; j++) {
            int c = nbase + tx + 16*j;
            float2 sv = unpack2(sacc[i][j]);
            float val = sv.x + sv.y + bsec[c];
            if (sec == 0) {
                d_q[(((size_t)b*HH + (c >> 5))*SS + srow)*HD + (c & 31)] = val;
            } else if (sec == 1) {
                d_k[(((size_t)b*HH + (c >> 5))*SS + srow)*HD + (c & 31)] = val * SCALE;
            } else {
                d_v[(size_t)gm*CC + c] = val;
            }
        }
    }
}

// ---------------------------------------------------------------------------
// Kernel 2: bf16 mma.sync attention (FA2-style, split-bf16 PV).
// Block: 256 thr, 128 q rows of one (b,h). Loop 50 key tiles of 64.
//   QK : S = Qbf . Kbf^T                      (m16n8k16, fp32 acc)
//   epi: w = (mask+1e-6)*exp(s), rowsum, W -> bf16 hi/lo A-fragments
//   PV : O += Whi.Vhi + Whi.Vlo + Wlo.Vhi     (V == K, transposed in smem)
// ---------------------------------------------------------------------------
__global__ void __launch_bounds__(256, 2) attn_mma_kernel(const float* __restrict__ mask)
{
    __shared__ __align__(16) u16 Qsm[128*40];   // 10240 B, q rows x 32 bf16 (stride 40)
    __shared__ __align__(16) u16 Ksm[64*40];    //  5120 B, key rows x 32 bf16 hi
    __shared__ __align__(16) u16 Vth[32*72];    //  4608 B, dim rows x 64 keys bf16 hi
    __shared__ __align__(16) u16 Vtl[32*72];    //  4608 B, lo part

    const int t = threadIdx.x;
    const int w = t >> 5, lane = t & 31;
    const int g = lane >> 2, t4 = lane & 3;
    const int bh = blockIdx.x, b = bh >> 3, h = bh & 7;
    const int q0 = blockIdx.y * 128;

    const float* qbase = d_q + (size_t)bh * SS * HD;
    const float* kbase = d_k + (size_t)bh * SS * HD;

    // ---- stage Q tile to smem as bf16 ----
    for (int idx = t; idx < 128*8; idx += 256) {
        int r = idx >> 3, c4 = (idx & 7) * 4;
        int gq = q0 + r;
        float4 v = make_float4(0.f, 0.f, 0.f, 0.f);
        if (gq < SS) v = *(const float4*)(qbase + (size_t)gq*HD + c4);
        *(u32*)&Qsm[r*40 + c4]     = pack_bf2(v.x, v.y);
        *(u32*)&Qsm[r*40 + c4 + 2] = pack_bf2(v.z, v.w);
    }
    __syncthreads();

    // ---- Q A-fragments (2 k-steps x 4 regs), held in registers ----
    u32 qa[2][4];
    {
        u32 qs = smem_u32(Qsm);
        int row = 16*w + (lane & 15);
        int cb = (lane >> 4) * 8;
        ldx4(qa[0], qs + (u32)(row*40 + cb) * 2);
        ldx4(qa[1], qs + (u32)(row*40 + cb + 16) * 2);
    }

    const u32 ks_s  = smem_u32(Ksm);
    const u32 vth_s = smem_u32(Vth);
    const u32 vtl_s = smem_u32(Vtl);

    const int r0 = q0 + 16*w + g;
    const int r1i = r0 + 8;
    const float* mbb = mask + (size_t)b * SS * SS;
    const float* mr0 = (r0  < SS) ? mbb + (size_t)r0 * SS : (const float*)0;
    const float* mr1 = (r1i < SS) ? mbb + (size_t)r1i * SS : (const float*)0;

    float oacc[4][4];
    #pragma unroll
    for (int i = 0; i < 4; i++)
        #pragma unroll
        for (int c = 0; c < 4; c++) oacc[i][c] = 0.f;
    float rs0 = 0.f, rs1 = 0.f;

    for (int kt = 0; kt < NKT2; kt++) {
        const int k0 = kt * 64;
        __syncthreads();   // protect smem from previous iteration's readers
        // ---- cooperative load + convert K tile (64 keys x 32 dims) ----
        {
            int kk = t >> 2, d0 = (t & 3) * 8;
            int gk = k0 + kk;
            float v[8];
            if (gk < SS) {
                *(float4*)&v[0] = *(const float4*)(kbase + (size_t)gk*HD + d0);
                *(float4*)&v[4] = *(const float4*)(kbase + (size_t)gk*HD + d0 + 4);
            } else {
                #pragma unroll
                for (int i = 0; i < 8; i++) v[i] = 0.f;
            }
            #pragma unroll
            for (int i = 0; i < 4; i++)
                *(u32*)&Ksm[kk*40 + d0 + 2*i] = pack_bf2(v[2*i], v[2*i+1]);
            #pragma unroll
            for (int i = 0; i < 8; i++) {
                u16 hb = f2bf(v[i]);
                u16 lb = f2bf(v[i] - bf2f(hb));
                Vth[(d0+i)*72 + kk] = hb;
                Vtl[(d0+i)*72 + kk] = lb;
            }
        }
        __syncthreads();

        // ---- per 16-key chunk: QK mma -> epilogue -> PV mma ----
        #pragma unroll
        for (int j = 0; j < 4; j++) {
            float sc[2][4];
            #pragma unroll
            for (int p = 0; p < 2; p++) {
                #pragma unroll
                for (int c = 0; c < 4; c++) sc[p][c] = 0.f;
                int nt = 2*j + p;
                #pragma unroll
                for (int ks2 = 0; ks2 < 2; ks2++) {
                    u32 b0, b1;
                    u32 addr = ks_s + (u32)(((nt*8) + (lane & 7))*40
                                            + ks2*16 + ((lane >> 3) & 1)*8) * 2;
                    ldx2(b0, b1, addr);
                    mma16816(sc[p], qa[ks2], b0, b1);
                }
            }
            // epilogue for key columns [k0+16j, k0+16j+16)
            u32 wh[4], wl[4];
            #pragma unroll
            for (int p = 0; p < 2; p++) {
                int gk = k0 + (2*j + p)*8 + 2*t4;
                float w00 = 0.f, w01 = 0.f, w10 = 0.f, w11 = 0.f;
                if (gk < SS) {
                    if (mr0) {
                        float2 m = *(const float2*)(mr0 + gk);
                        w00 = (m.x + 1e-6f) * __expf(sc[p][0]);
                        w01 = (m.y + 1e-6f) * __expf(sc[p][1]);
                    }
                    if (mr1) {
                        float2 m = *(const float2*)(mr1 + gk);
                        w10 = (m.x + 1e-6f) * __expf(sc[p][2]);
                        w11 = (m.y + 1e-6f) * __expf(sc[p][3]);
                    }
                }
                rs0 += w00 + w01;
                rs1 += w10 + w11;
                u32 h0 = pack_bf2(w00, w01);
                u32 h1 = pack_bf2(w10, w11);
                wh[2*p]   = h0;
                wh[2*p+1] = h1;
                float l00 = w00 - bf2f((u16)(h0 & 0xFFFF));
                float l01 = w01 - bf2f((u16)(h0 >> 16));
                float l10 = w10 - bf2f((u16)(h1 & 0xFFFF));
                float l11 = w11 - bf2f((u16)(h1 >> 16));
                wl[2*p]   = pack_bf2(l00, l01);
                wl[2*p+1] = pack_bf2(l10, l11);
            }
            // PV for this k-step over 4 output d-tiles
            #pragma unroll
            for (int i = 0; i < 4; i++) {
                u32 a_off = (u32)((i*8 + (lane & 7))*72
                                  + j*16 + ((lane >> 3) & 1)*8) * 2;
                u32 bh0, bh1, bl0, bl1;
                ldx2(bh0, bh1, vth_s + a_off);
                ldx2(bl0, bl1, vtl_s + a_off);
                mma16816(oacc[i], wh, bh0, bh1);
                mma16816(oacc[i], wh, bl0, bl1);
                mma16816(oacc[i], wl, bh0, bh1);
            }
        }
    }

    // ---- rowsum reduce across the 4 lanes of each row group ----
    rs0 += __shfl_xor_sync(0xffffffffu, rs0, 1);
    rs0 += __shfl_xor_sync(0xffffffffu, rs0, 2);
    rs1 += __shfl_xor_sync(0xffffffffu, rs1, 1);
    rs1 += __shfl_xor_sync(0xffffffffu, rs1, 2);
    float inv0 = 1.0f / rs0;
    float inv1 = 1.0f / rs1;

    if (r0 < SS) {
        float* o = d_acc + ((size_t)b*SS + r0)*CC + h*HD + 2*t4;
        #pragma unroll
        for (int i = 0; i < 4; i++)
            *(float2*)(o + i*8) = make_float2(oacc[i][0]*inv0, oacc[i][1]*inv0);
    }
    if (r1i < SS) {
        float* o = d_acc + ((size_t)b*SS + r1i)*CC + h*HD + 2*t4;
        #pragma unroll
        for (int i = 0; i < 4; i++)
            *(float2*)(o + i*8) = make_float2(oacc[i][2]*inv1, oacc[i][3]*inv1);
    }
}

// ---------------------------------------------------------------------------
// Kernel 3: LEPE depthwise 5x5 conv on v[:, QN:], accumulated into d_acc
// ---------------------------------------------------------------------------
__global__ __launch_bounds__(256) void lepe_kernel(
    const float* __restrict__ lw, const float* __restrict__ lb)
{
    int blk = blockIdx.x;
    int b = blk / 3136, p = blk % 3136;
    int y = p / 56, x = p % 56;
    int c = threadIdx.x;
    float a = lb[c];
    #pragma unroll
    for (int ky = 0; ky < 5; ky++) {
        int iy = y + ky - 2;
        if (iy < 0 || iy >= 56) continue;
        #pragma unroll
        for (int kx = 0; kx < 5; kx++) {
            int ix = x + kx - 2;
            if (ix < 0 || ix >= 56) continue;
            a += d_v[((size_t)b*SS + QN + iy*56 + ix)*CC + c] * lw[(ky*5 + kx)*CC + c];
        }
    }
    d_acc[((size_t)b*SS + QN + p)*CC + c] += a;
}

// ---------------------------------------------------------------------------
// Kernel 4: output projection (f32x2 tiles)
// ---------------------------------------------------------------------------
__global__ __launch_bounds__(256) void out_kernel(
    const float* __restrict__ wo, const float* __restrict__ bo, float* __restrict__ out)
{
    __shared__ float Xs[64][36];
    __shared__ float Wt[64][36];
    int m0 = blockIdx.x * 64;
    int n0 = blockIdx.y * 64;
    int t = threadIdx.x;
    int ty = t >> 4, tx = t & 15;

    u64 sacc[4][4];
    #pragma unroll
    for (int i = 0; i < 4; i++)
        #pragma unroll
        for (int j = 0; j < 4; j++) sacc[i][j] = 0ull;

    for (int kk = 0; kk < CC; kk += 32) {
        __syncthreads();
        for (int f = t; f < 64*32/4; f += 256) {
            int r = f >> 3, c4 = (f & 7) << 2;
            int gm = m0 + r;
            float4 v = make_float4(0.f, 0.f, 0.f, 0.f);
            if (gm < MTOT) v = *(const float4*)(d_acc + (size_t)gm*CC + kk + c4);
            *(float4*)&Xs[r][c4] = v;
            *(float4*)&Wt[r][c4] = *(const float4*)(wo + (size_t)(n0 + r)*CC + kk + c4);
        }
        __syncthreads();
        #pragma unroll
        for (int d = 0; d < 32; d += 4) {
            u64 xr[4][2], wr[4][2];
            #pragma unroll
            for (int i = 0; i < 4; i++) {
                ulonglong2 v2 = *(const ulonglong2*)&Xs[ty + 16*i][d];
                xr[i][0] = v2.x; xr[i][1] = v2.y;
            }
            #pragma unroll
            for (int j = 0; j < 4; j++) {
                ulonglong2 v2 = *(const ulonglong2*)&Wt[tx + 16*j][d];
                wr[j][0] = v2.x; wr[j][1] = v2.y;
            }
            #pragma unroll
            for (int i = 0; i < 4; i++)
                #pragma unroll
                for (int j = 0; j < 4; j++) {
                    fma2(sacc[i][j], xr[i][0], wr[j][0]);
                    fma2(sacc[i][j], xr[i][1], wr[j][1]);
                }
        }
    }
    #pragma unroll
    for (int i = 0; i < 4; i++) {
        int gm = m0 + ty + 16*i;
        if (gm >= MTOT) continue;
        #pragma unroll
        for (int j = 0; j < 4; j++) {
            int n = n0 + tx + 16*j;
            float2 sv = unpack2(sacc[i][j]);
            out[(size_t)gm*CC + n] = sv.x + sv.y + bo[n];
        }
    }
}

// ---------------------------------------------------------------------------
extern "C" void kernel_launch(void* const* d_in, const int* in_sizes, int n_in,
                              void* d_out, int out_size) {
    const float* x    = (const float*)d_in[0];
    const float* mask = (const float*)d_in[1];
    const float* wq   = (const float*)d_in[2];
    const float* bq   = (const float*)d_in[3];
    const float* wk   = (const float*)d_in[4];
    const float* bk   = (const float*)d_in[5];
    const float* wv   = (const float*)d_in[6];
    const float* bv   = (const float*)d_in[7];
    const float* lw   = (const float*)d_in[8];
    const float* lb   = (const float*)d_in[9];
    const float* wo   = (const float*)d_in[10];
    const float* bo   = (const float*)d_in[11];
    float* out = (float*)d_out;

    dim3 g1(99, 12);
    qkv_kernel<<<g1, 256>>>(x, wq, bq, wk, bk, wv, bv);
    dim3 g2(BB*HH, NQT);
    attn_mma_kernel<<<g2, 256>>>(mask);
    lepe_kernel<<<BB*3136, 256>>>(lw, lb);
    dim3 g4(99, 4);
    out_kernel<<<g4, 256>>>(wo, bo, out);
}

// round 4
// speedup vs baseline: 3.8846x; 2.0103x over previous
#include <cuda_runtime.h>
#include <cuda_fp16.h>
#include <cstdint>

#define BB 2
#define SS 3144
#define CC 256
#define HH 8
#define HD 32
#define QN 8
#define MTOT (BB*SS)            /* 6288 */
#define SCALE 0.1767766952966369f
#define NKT2 ((SS + 63) / 64)   /* 50 key tiles of 64 */
#define NQT64 ((SS + 63) / 64)  /* 50 query tiles of 64 */

__device__ __half d_qh[BB*HH*SS*HD];  // head-major fp16: ((b*H+h)*S + s)*HD + d
__device__ __half d_kh[BB*HH*SS*HD];  // pre-scaled by SCALE (used as K and V)
__device__ float  d_v[BB*SS*CC];      // (b,s,c)
__device__ float  d_acc[BB*SS*CC];    // attention out (+lepe) before final proj

typedef unsigned long long u64;
typedef unsigned int u32;
typedef unsigned short u16;

// ---------------- f32x2 helpers (for the GEMM kernels) ----------------
__device__ __forceinline__ void fma2(u64 &d, u64 a, u64 b) {
    asm("fma.rn.f32x2 %0, %1, %2, %0;" : "+l"(d) : "l"(a), "l"(b));
}
__device__ __forceinline__ float2 unpack2(u64 v) {
    float2 r; asm("mov.b64 {%0, %1}, %2;" : "=f"(r.x), "=f"(r.y) : "l"(v)); return r;
}

// ---------------- fp16 / mma helpers ----------------
__device__ __forceinline__ u32 smem_u32(const void* p) {
    u32 a;
    asm("{ .reg .u64 t; cvta.to.shared.u64 t, %1; cvt.u32.u64 %0, t; }" : "=r"(a) : "l"(p));
    return a;
}
// returns hi<<16 | lo  (lo = first/even element in memory & fragment order)
__device__ __forceinline__ u32 pack_h2(float lo, float hi) {
    u32 r; asm("cvt.rn.f16x2.f32 %0, %1, %2;" : "=r"(r) : "f"(hi), "f"(lo)); return r;
}
__device__ __forceinline__ void ldx2(u32 &r0, u32 &r1, u32 saddr) {
    asm volatile("ldmatrix.sync.aligned.m8n8.x2.shared.b16 {%0,%1}, [%2];"
                 : "=r"(r0), "=r"(r1) : "r"(saddr));
}
__device__ __forceinline__ void ldx4(u32* r, u32 saddr) {
    asm volatile("ldmatrix.sync.aligned.m8n8.x4.shared.b16 {%0,%1,%2,%3}, [%4];"
                 : "=r"(r[0]), "=r"(r[1]), "=r"(r[2]), "=r"(r[3]) : "r"(saddr));
}
__device__ __forceinline__ void mma_h(float* c, const u32* a, u32 b0, u32 b1) {
    asm volatile("mma.sync.aligned.m16n8k16.row.col.f32.f16.f16.f32 "
                 "{%0,%1,%2,%3}, {%4,%5,%6,%7}, {%8,%9}, {%0,%1,%2,%3};"
                 : "+f"(c[0]), "+f"(c[1]), "+f"(c[2]), "+f"(c[3])
                 : "r"(a[0]), "r"(a[1]), "r"(a[2]), "r"(a[3]), "r"(b0), "r"(b1));
}

// ---------------------------------------------------------------------------
// Kernel 1: fused QKV projection (f32x2 tiles); q/k written as fp16 head-major
// ---------------------------------------------------------------------------
__global__ __launch_bounds__(256) void qkv_kernel(
    const float* __restrict__ x,
    const float* __restrict__ wq, const float* __restrict__ bq,
    const float* __restrict__ wk, const float* __restrict__ bk,
    const float* __restrict__ wv, const float* __restrict__ bv)
{
    __shared__ float Xs[64][36];
    __shared__ float Wt[64][36];
    int m0 = blockIdx.x * 64;
    int n0 = blockIdx.y * 64;
    int t = threadIdx.x;
    int ty = t >> 4, tx = t & 15;

    int sec = n0 >> 8;
    const float* wsec = (sec == 0) ? wq : (sec == 1) ? wk : wv;
    const float* bsec = (sec == 0) ? bq : (sec == 1) ? bk : bv;
    int nbase = n0 & 255;

    u64 sacc[4][4];
    #pragma unroll
    for (int i = 0; i < 4; i++)
        #pragma unroll
        for (int j = 0; j < 4; j++) sacc[i][j] = 0ull;

    for (int kk = 0; kk < CC; kk += 32) {
        __syncthreads();
        for (int f = t; f < 64*32/4; f += 256) {
            int r = f >> 3, c4 = (f & 7) << 2;
            int gm = m0 + r;
            float4 v = make_float4(0.f, 0.f, 0.f, 0.f);
            if (gm < MTOT) v = *(const float4*)(x + (size_t)gm*CC + kk + c4);
            *(float4*)&Xs[r][c4] = v;
            *(float4*)&Wt[r][c4] = *(const float4*)(wsec + (size_t)(nbase + r)*CC + kk + c4);
        }
        __syncthreads();
        #pragma unroll
        for (int d = 0; d < 32; d += 4) {
            u64 xr[4][2], wr[4][2];
            #pragma unroll
            for (int i = 0; i < 4; i++) {
                ulonglong2 v2 = *(const ulonglong2*)&Xs[ty + 16*i][d];
                xr[i][0] = v2.x; xr[i][1] = v2.y;
            }
            #pragma unroll
            for (int j = 0; j < 4; j++) {
                ulonglong2 v2 = *(const ulonglong2*)&Wt[tx + 16*j][d];
                wr[j][0] = v2.x; wr[j][1] = v2.y;
            }
            #pragma unroll
            for (int i = 0; i < 4; i++)
                #pragma unroll
                for (int j = 0; j < 4; j++) {
                    fma2(sacc[i][j], xr[i][0], wr[j][0]);
                    fma2(sacc[i][j], xr[i][1], wr[j][1]);
                }
        }
    }
    #pragma unroll
    for (int i = 0; i < 4; i++) {
        int gm = m0 + ty + 16*i;
        if (gm >= MTOT) continue;
        int b = gm / SS, srow = gm % SS;
        #pragma unroll
        for (int j = 0; j < 4; j++) {
            int c = nbase + tx + 16*j;
            float2 sv = unpack2(sacc[i][j]);
            float val = sv.x + sv.y + bsec[c];
            if (sec == 0) {
                d_qh[(((size_t)b*HH + (c >> 5))*SS + srow)*HD + (c & 31)] = __float2half(val);
            } else if (sec == 1) {
                d_kh[(((size_t)b*HH + (c >> 5))*SS + srow)*HD + (c & 31)] = __float2half(val * SCALE);
            } else {
                d_v[(size_t)gm*CC + c] = val;
            }
        }
    }
}

// ---------------------------------------------------------------------------
// Kernel 2: fp16 mma.sync attention (FA-style, single-pass fp16 PV).
// Block: 128 thr (4 warps), 64 q rows of one (b,h). Loop 50 key tiles of 64.
//   QK : S = Qh . Kh^T                      (m16n8k16 f16, fp32 acc)
//   epi: w = (mask+1e-6)*exp(s), rowsum; W -> fp16 A-fragments (in regs)
//   PV : O += W . V^T                       (V == K, transposed in smem)
// Mask float2s are prefetched one 16-key chunk ahead into registers.
// ---------------------------------------------------------------------------
__global__ void __launch_bounds__(128, 5) attn_mma_kernel(const float* __restrict__ mask)
{
    __shared__ __align__(16) u16 Qsm[64*40];   // 5120 B, q rows x 32 fp16 (stride 40)
    __shared__ __align__(16) u16 Ksm[64*40];   // 5120 B, key rows x 32 fp16
    __shared__ __align__(16) u16 Vt[32*72];    // 4608 B, dim rows x 64 keys fp16

    const int t = threadIdx.x;
    const int w = t >> 5, lane = t & 31;
    const int g = lane >> 2, t4 = lane & 3;
    const int bh = blockIdx.x, b = bh >> 3, h = bh & 7;
    const int q0 = blockIdx.y * 64;

    const __half* qbase = d_qh + (size_t)bh * SS * HD;
    const __half* kbase = d_kh + (size_t)bh * SS * HD;

    // ---- stage Q tile to smem (already fp16) ----
    for (int idx = t; idx < 64*4; idx += 128) {
        int r = idx >> 2, qu = idx & 3;           // 4 x uint4 (8 halves) per row
        int gq = q0 + r;
        uint4 v = make_uint4(0u, 0u, 0u, 0u);
        if (gq < SS) v = *(const uint4*)(qbase + (size_t)gq*HD + qu*8);
        *(uint4*)&Qsm[r*40 + qu*8] = v;
    }
    __syncthreads();

    // ---- Q A-fragments (2 k-steps x 4 regs), held in registers ----
    u32 qa[2][4];
    {
        u32 qs = smem_u32(Qsm);
        int row = 16*w + (lane & 15);
        int cb = (lane >> 4) * 8;
        ldx4(qa[0], qs + (u32)(row*40 + cb) * 2);
        ldx4(qa[1], qs + (u32)(row*40 + cb + 16) * 2);
    }

    const u32 ks_s = smem_u32(Ksm);
    const u32 vt_s = smem_u32(Vt);

    const int r0  = q0 + 16*w + g;
    const int r1i = r0 + 8;
    const float* mbb = mask + (size_t)b * SS * SS;
    const float* mr0 = (r0  < SS) ? mbb + (size_t)r0  * SS : (const float*)0;
    const float* mr1 = (r1i < SS) ? mbb + (size_t)r1i * SS : (const float*)0;

    float oacc[4][4];
    #pragma unroll
    for (int i = 0; i < 4; i++)
        #pragma unroll
        for (int c = 0; c < 4; c++) oacc[i][c] = 0.f;
    float rs0 = 0.f, rs1 = 0.f;

    // mask prefetch double-buffer (one 16-key chunk ahead)
    float2 mbuf[2][4];
    auto do_pref = [&](int gjdx, float2* dst) {
        int nkt = gjdx >> 2, nj = gjdx & 3;
        int base = nkt*64 + nj*16;
        #pragma unroll
        for (int p = 0; p < 2; p++) {
            int gk = base + p*8 + 2*t4;
            bool v = gk < SS;
            dst[2*p]   = (v && mr0) ? *(const float2*)(mr0 + gk)
                                    : make_float2(-1e-6f, -1e-6f);
            dst[2*p+1] = (v && mr1) ? *(const float2*)(mr1 + gk)
                                    : make_float2(-1e-6f, -1e-6f);
        }
    };
    do_pref(0, mbuf[0]);

    for (int kt = 0; kt < NKT2; kt++) {
        const int k0 = kt * 64;
        __syncthreads();   // protect smem from previous iteration's readers
        // ---- cooperative load K tile (fp16 already): Ksm rows + Vt transpose ----
        {
            int kk = t & 63, d0 = (t >> 6) * 16;
            int gk = k0 + kk;
            uint4 a0 = make_uint4(0u,0u,0u,0u), a1 = make_uint4(0u,0u,0u,0u);
            if (gk < SS) {
                a0 = *(const uint4*)(kbase + (size_t)gk*HD + d0);
                a1 = *(const uint4*)(kbase + (size_t)gk*HD + d0 + 8);
            }
            *(uint4*)&Ksm[kk*40 + d0]     = a0;
            *(uint4*)&Ksm[kk*40 + d0 + 8] = a1;
            u32 wds[8] = {a0.x, a0.y, a0.z, a0.w, a1.x, a1.y, a1.z, a1.w};
            #pragma unroll
            for (int i = 0; i < 8; i++) {
                int d = d0 + 2*i;
                Vt[d*72 + kk]     = (u16)(wds[i] & 0xFFFF);
                Vt[(d+1)*72 + kk] = (u16)(wds[i] >> 16);
            }
        }
        __syncthreads();

        // ---- per 16-key chunk: QK mma -> epilogue -> PV mma ----
        #pragma unroll
        for (int j = 0; j < 4; j++) {
            const float2* mc = mbuf[j & 1];
            float sc[2][4];
            #pragma unroll
            for (int p = 0; p < 2; p++) {
                #pragma unroll
                for (int c = 0; c < 4; c++) sc[p][c] = 0.f;
                int nt = 2*j + p;
                #pragma unroll
                for (int ks2 = 0; ks2 < 2; ks2++) {
                    u32 b0, b1;
                    u32 addr = ks_s + (u32)(((nt*8) + (lane & 7))*40
                                            + ks2*16 + ((lane >> 3) & 1)*8) * 2;
                    ldx2(b0, b1, addr);
                    mma_h(sc[p], qa[ks2], b0, b1);
                }
            }
            // prefetch next chunk's mask (covers L2 latency with epi+PV work)
            {
                int gn = kt*4 + j + 1;
                if (gn < NKT2*4) do_pref(gn, mbuf[(j+1) & 1]);
            }
            // epilogue for key columns [k0+16j, k0+16j+16)
            u32 wh[4];
            #pragma unroll
            for (int p = 0; p < 2; p++) {
                float2 m0 = mc[2*p], m1 = mc[2*p+1];
                float w00 = (m0.x + 1e-6f) * __expf(sc[p][0]);
                float w01 = (m0.y + 1e-6f) * __expf(sc[p][1]);
                float w10 = (m1.x + 1e-6f) * __expf(sc[p][2]);
                float w11 = (m1.y + 1e-6f) * __expf(sc[p][3]);
                rs0 += w00 + w01;
                rs1 += w10 + w11;
                wh[2*p]   = pack_h2(w00, w01);
                wh[2*p+1] = pack_h2(w10, w11);
            }
            // PV for this k-step over 4 output d-tiles
            #pragma unroll
            for (int i = 0; i < 4; i++) {
                u32 a_off = (u32)((i*8 + (lane & 7))*72
                                  + j*16 + ((lane >> 3) & 1)*8) * 2;
                u32 bv0, bv1;
                ldx2(bv0, bv1, vt_s + a_off);
                mma_h(oacc[i], wh, bv0, bv1);
            }
        }
    }

    // ---- rowsum reduce across the 4 lanes of each row group ----
    rs0 += __shfl_xor_sync(0xffffffffu, rs0, 1);
    rs0 += __shfl_xor_sync(0xffffffffu, rs0, 2);
    rs1 += __shfl_xor_sync(0xffffffffu, rs1, 1);
    rs1 += __shfl_xor_sync(0xffffffffu, rs1, 2);
    float inv0 = 1.0f / rs0;
    float inv1 = 1.0f / rs1;

    if (r0 < SS) {
        float* o = d_acc + ((size_t)b*SS + r0)*CC + h*HD + 2*t4;
        #pragma unroll
        for (int i = 0; i < 4; i++)
            *(float2*)(o + i*8) = make_float2(oacc[i][0]*inv0, oacc[i][1]*inv0);
    }
    if (r1i < SS) {
        float* o = d_acc + ((size_t)b*SS + r1i)*CC + h*HD + 2*t4;
        #pragma unroll
        for (int i = 0; i < 4; i++)
            *(float2*)(o + i*8) = make_float2(oacc[i][2]*inv1, oacc[i][3]*inv1);
    }
}

// ---------------------------------------------------------------------------
// Kernel 3: LEPE depthwise 5x5 conv on v[:, QN:], accumulated into d_acc
// ---------------------------------------------------------------------------
__global__ __launch_bounds__(256) void lepe_kernel(
    const float* __restrict__ lw, const float* __restrict__ lb)
{
    int blk = blockIdx.x;
    int b = blk / 3136, p = blk % 3136;
    int y = p / 56, x = p % 56;
    int c = threadIdx.x;
    float a = lb[c];
    #pragma unroll
    for (int ky = 0; ky < 5; ky++) {
        int iy = y + ky - 2;
        if (iy < 0 || iy >= 56) continue;
        #pragma unroll
        for (int kx = 0; kx < 5; kx++) {
            int ix = x + kx - 2;
            if (ix < 0 || ix >= 56) continue;
            a += d_v[((size_t)b*SS + QN + iy*56 + ix)*CC + c] * lw[(ky*5 + kx)*CC + c];
        }
    }
    d_acc[((size_t)b*SS + QN + p)*CC + c] += a;
}

// ---------------------------------------------------------------------------
// Kernel 4: output projection (f32x2 tiles)
// ---------------------------------------------------------------------------
__global__ __launch_bounds__(256) void out_kernel(
    const float* __restrict__ wo, const float* __restrict__ bo, float* __restrict__ out)
{
    __shared__ float Xs[64][36];
    __shared__ float Wt[64][36];
    int m0 = blockIdx.x * 64;
    int n0 = blockIdx.y * 64;
    int t = threadIdx.x;
    int ty = t >> 4, tx = t & 15;

    u64 sacc[4][4];
    #pragma unroll
    for (int i = 0; i < 4; i++)
        #pragma unroll
        for (int j = 0; j < 4; j++) sacc[i][j] = 0ull;

    for (int kk = 0; kk < CC; kk += 32) {
        __syncthreads();
        for (int f = t; f < 64*32/4; f += 256) {
            int r = f >> 3, c4 = (f & 7) << 2;
            int gm = m0 + r;
            float4 v = make_float4(0.f, 0.f, 0.f, 0.f);
            if (gm < MTOT) v = *(const float4*)(d_acc + (size_t)gm*CC + kk + c4);
            *(float4*)&Xs[r][c4] = v;
            *(float4*)&Wt[r][c4] = *(const float4*)(wo + (size_t)(n0 + r)*CC + kk + c4);
        }
        __syncthreads();
        #pragma unroll
        for (int d = 0; d < 32; d += 4) {
            u64 xr[4][2], wr[4][2];
            #pragma unroll
            for (int i = 0; i < 4; i++) {
                ulonglong2 v2 = *(const ulonglong2*)&Xs[ty + 16*i][d];
                xr[i][0] = v2.x; xr[i][1] = v2.y;
            }
            #pragma unroll
            for (int j = 0; j < 4; j++) {
                ulonglong2 v2 = *(const ulonglong2*)&Wt[tx + 16*j][d];
                wr[j][0] = v2.x; wr[j][1] = v2.y;
            }
            #pragma unroll
            for (int i = 0; i < 4; i++)
                #pragma unroll
                for (int j = 0; j < 4; j++) {
                    fma2(sacc[i][j], xr[i][0], wr[j][0]);
                    fma2(sacc[i][j], xr[i][1], wr[j][1]);
                }
        }
    }
    #pragma unroll
    for (int i = 0; i < 4; i++) {
        int gm = m0 + ty + 16*i;
        if (gm >= MTOT) continue;
        #pragma unroll
        for (int j = 0; j < 4; j++) {
            int n = n0 + tx + 16*j;
            float2 sv = unpack2(sacc[i][j]);
            out[(size_t)gm*CC + n] = sv.x + sv.y + bo[n];
        }
    }
}

// ---------------------------------------------------------------------------
extern "C" void kernel_launch(void* const* d_in, const int* in_sizes, int n_in,
                              void* d_out, int out_size) {
    const float* x    = (const float*)d_in[0];
    const float* mask = (const float*)d_in[1];
    const float* wq   = (const float*)d_in[2];
    const float* bq   = (const float*)d_in[3];
    const float* wk   = (const float*)d_in[4];
    const float* bk   = (const float*)d_in[5];
    const float* wv   = (const float*)d_in[6];
    const float* bv   = (const float*)d_in[7];
    const float* lw   = (const float*)d_in[8];
    const float* lb   = (const float*)d_in[9];
    const float* wo   = (const float*)d_in[10];
    const float* bo   = (const float*)d_in[11];
    float* out = (float*)d_out;

    dim3 g1(99, 12);
    qkv_kernel<<<g1, 256>>>(x, wq, bq, wk, bk, wv, bv);
    dim3 g2(BB*HH, NQT64);
    attn_mma_kernel<<<g2, 128>>>(mask);
    lepe_kernel<<<BB*3136, 256>>>(lw, lb);
    dim3 g4(99, 4);
    out_kernel<<<g4, 256>>>(wo, bo, out);
}

// round 5
// speedup vs baseline: 4.9900x; 1.2846x over previous
#include <cuda_runtime.h>
#include <cuda_fp16.h>
#include <cstdint>

#define BB 2
#define SS 3144
#define CC 256
#define HH 8
#define HD 32
#define QN 8
#define MTOT (BB*SS)            /* 6288 */
#define SCALE 0.1767766952966369f
#define NKT2 ((SS + 63) / 64)   /* 50 key tiles of 64 */
#define NQT64 ((SS + 63) / 64)  /* 50 query tiles of 64 */
#define NX (MTOT*CC)

typedef unsigned long long u64;
typedef unsigned int u32;
typedef unsigned short u16;

__device__ __align__(16) __half d_qh[BB*HH*SS*HD];  // head-major fp16
__device__ __align__(16) __half d_kh[BB*HH*SS*HD];  // pre-scaled by SCALE (K and V)
__device__ __align__(16) float  d_v[BB*SS*CC];
__device__ __align__(16) float  d_acc[BB*SS*CC];    // attention out (f32)
__device__ __align__(16) __half d_xh[NX];           // x split hi/lo
__device__ __align__(16) __half d_xl[NX];
__device__ __align__(16) __half d_wh[768*CC];       // [wq;wk;wv] split
__device__ __align__(16) __half d_wl[768*CC];
__device__ __align__(16) __half d_woh[CC*CC];       // wo split
__device__ __align__(16) __half d_wol[CC*CC];
__device__ __align__(16) __half d_acch[BB*SS*CC];   // acc(+lepe) split
__device__ __align__(16) __half d_accl[BB*SS*CC];

// ---------------- helpers ----------------
__device__ __forceinline__ u32 smem_u32(const void* p) {
    u32 a;
    asm("{ .reg .u64 t; cvta.to.shared.u64 t, %1; cvt.u32.u64 %0, t; }" : "=r"(a) : "l"(p));
    return a;
}
__device__ __forceinline__ u32 pack_h2(float lo, float hi) {
    u32 r; asm("cvt.rn.f16x2.f32 %0, %1, %2;" : "=r"(r) : "f"(hi), "f"(lo)); return r;
}
__device__ __forceinline__ void ldx4(u32* r, u32 saddr) {
    asm volatile("ldmatrix.sync.aligned.m8n8.x4.shared.b16 {%0,%1,%2,%3}, [%4];"
                 : "=r"(r[0]), "=r"(r[1]), "=r"(r[2]), "=r"(r[3]) : "r"(saddr));
}
__device__ __forceinline__ void ldx4t(u32* r, u32 saddr) {
    asm volatile("ldmatrix.sync.aligned.m8n8.x4.trans.shared.b16 {%0,%1,%2,%3}, [%4];"
                 : "=r"(r[0]), "=r"(r[1]), "=r"(r[2]), "=r"(r[3]) : "r"(saddr));
}
__device__ __forceinline__ void mma_h(float* c, const u32* a, u32 b0, u32 b1) {
    asm volatile("mma.sync.aligned.m16n8k16.row.col.f32.f16.f16.f32 "
                 "{%0,%1,%2,%3}, {%4,%5,%6,%7}, {%8,%9}, {%0,%1,%2,%3};"
                 : "+f"(c[0]), "+f"(c[1]), "+f"(c[2]), "+f"(c[3])
                 : "r"(a[0]), "r"(a[1]), "r"(a[2]), "r"(a[3]), "r"(b0), "r"(b1));
}
__device__ __forceinline__ void split_h(float v, __half &h, __half &l) {
    h = __float2half_rn(v);
    l = __float2half_rn(v - __half2float(h));
}

// ---------------------------------------------------------------------------
// Kernel 0: split x, [wq;wk;wv], wo into fp16 hi/lo
// ---------------------------------------------------------------------------
__global__ __launch_bounds__(256) void cvt_kernel(
    const float* __restrict__ x,
    const float* __restrict__ wq, const float* __restrict__ wk,
    const float* __restrict__ wv, const float* __restrict__ wo)
{
    int idx = blockIdx.x * 256 + threadIdx.x;
    if (idx < NX) {
        __half h, l; split_h(x[idx], h, l);
        d_xh[idx] = h; d_xl[idx] = l;
    } else {
        int j = idx - NX;                 // 0 .. 4*65536-1
        int sec = j >> 16, off = j & 65535;
        const float* src = (sec == 0) ? wq : (sec == 1) ? wk : (sec == 2) ? wv : wo;
        __half h, l; split_h(src[off], h, l);
        if (sec < 3) { d_wh[j] = h; d_wl[j] = l; }
        else         { d_woh[off] = h; d_wol[off] = l; }
    }
}

// ---------------------------------------------------------------------------
// Kernel 1: fused QKV projection, split-fp16 HMMA (3-pass).
// 64x64 tiles, 256 thr (8 warps: wr=w>>1 row-16 tile, wc=w&1 col-32 half).
// ---------------------------------------------------------------------------
__global__ __launch_bounds__(256) void qkv_kernel(
    const float* __restrict__ bq, const float* __restrict__ bk,
    const float* __restrict__ bv)
{
    __shared__ __align__(16) u16 Xh[64*40];
    __shared__ __align__(16) u16 Xl[64*40];
    __shared__ __align__(16) u16 Wh[64*40];
    __shared__ __align__(16) u16 Wl[64*40];

    const int m0 = blockIdx.x * 64;
    const int n0 = blockIdx.y * 64;       // global 0..767
    const int t = threadIdx.x;
    const int w = t >> 5, lane = t & 31;
    const int g = lane >> 2, t4 = lane & 3;
    const int wr = w >> 1, wc = w & 1;
    const int sec = n0 >> 8;
    const int nbase = n0 & 255;

    float acc[4][4];
    #pragma unroll
    for (int i = 0; i < 4; i++)
        #pragma unroll
        for (int c = 0; c < 4; c++) acc[i][c] = 0.f;

    const u32 xb  = smem_u32(Xh), xlb = smem_u32(Xl);
    const u32 wb  = smem_u32(Wh), wlb = smem_u32(Wl);

    for (int kk = 0; kk < CC; kk += 32) {
        __syncthreads();
        {
            int r = t >> 2, c8 = (t & 3) * 8;
            int gm = m0 + r;
            uint4 a = make_uint4(0u,0u,0u,0u), b = make_uint4(0u,0u,0u,0u);
            if (gm < MTOT) {
                a = *(const uint4*)&d_xh[(size_t)gm*CC + kk + c8];
                b = *(const uint4*)&d_xl[(size_t)gm*CC + kk + c8];
            }
            *(uint4*)&Xh[r*40 + c8] = a;
            *(uint4*)&Xl[r*40 + c8] = b;
            int wrow = n0 + r;
            *(uint4*)&Wh[r*40 + c8] = *(const uint4*)&d_wh[(size_t)wrow*CC + kk + c8];
            *(uint4*)&Wl[r*40 + c8] = *(const uint4*)&d_wl[(size_t)wrow*CC + kk + c8];
        }
        __syncthreads();

        u32 ax[2][4], al[2][4];
        #pragma unroll
        for (int ks = 0; ks < 2; ks++) {
            u32 aoff = (u32)(((16*wr + (lane & 15))*40 + ks*16 + ((lane>>4)&1)*8) * 2);
            ldx4(ax[ks], xb  + aoff);
            ldx4(al[ks], xlb + aoff);
        }
        #pragma unroll
        for (int ks = 0; ks < 2; ks++) {
            #pragma unroll
            for (int np = 0; np < 2; np++) {
                u32 boff = (u32)(((32*wc + np*16 + ((lane>>4)&1)*8 + (lane & 7))*40
                                  + ks*16 + ((lane>>3)&1)*8) * 2);
                u32 bh4[4], bl4[4];
                ldx4(bh4, wb  + boff);
                ldx4(bl4, wlb + boff);
                mma_h(acc[2*np],   ax[ks], bh4[0], bh4[1]);
                mma_h(acc[2*np],   ax[ks], bl4[0], bl4[1]);
                mma_h(acc[2*np],   al[ks], bh4[0], bh4[1]);
                mma_h(acc[2*np+1], ax[ks], bh4[2], bh4[3]);
                mma_h(acc[2*np+1], ax[ks], bl4[2], bl4[3]);
                mma_h(acc[2*np+1], al[ks], bh4[2], bh4[3]);
            }
        }
    }

    const float* bsec = (sec == 0) ? bq : (sec == 1) ? bk : bv;
    #pragma unroll
    for (int nt = 0; nt < 4; nt++) {
        int ct = 32*wc + 8*nt + 2*t4;
        int c = nbase + ct;
        float b0v = bsec[c], b1v = bsec[c+1];
        #pragma unroll
        for (int rr = 0; rr < 2; rr++) {
            int gm = m0 + 16*wr + g + rr*8;
            if (gm >= MTOT) continue;
            float v0 = acc[nt][2*rr]   + b0v;
            float v1 = acc[nt][2*rr+1] + b1v;
            int b = gm / SS, srow = gm % SS;
            if (sec == 0) {
                *(__half2*)&d_qh[(((size_t)b*HH + (c>>5))*SS + srow)*HD + (c&31)] =
                    __floats2half2_rn(v0, v1);
            } else if (sec == 1) {
                *(__half2*)&d_kh[(((size_t)b*HH + (c>>5))*SS + srow)*HD + (c&31)] =
                    __floats2half2_rn(v0*SCALE, v1*SCALE);
            } else {
                *(float2*)&d_v[(size_t)gm*CC + c] = make_float2(v0, v1);
            }
        }
    }
}

// ---------------------------------------------------------------------------
// Kernel 2: fp16 mma.sync attention, K double-buffered, PV via ldmatrix.trans.
// Block: 128 thr (4 warps), 64 q rows of one (b,h). Loop 50 key tiles of 64.
// ---------------------------------------------------------------------------
__global__ void __launch_bounds__(128, 5) attn_mma_kernel(const float* __restrict__ mask)
{
    __shared__ __align__(16) u16 Qsm[64*40];     // 5120 B
    __shared__ __align__(16) u16 Ksm[2*64*40];   // 10240 B, double-buffered

    const int t = threadIdx.x;
    const int w = t >> 5, lane = t & 31;
    const int g = lane >> 2, t4 = lane & 3;
    const int bh = blockIdx.x, b = bh >> 3, h = bh & 7;
    const int q0 = blockIdx.y * 64;

    const __half* qbase = d_qh + (size_t)bh * SS * HD;
    const __half* kbase = d_kh + (size_t)bh * SS * HD;

    // ---- stage Q tile ----
    for (int idx = t; idx < 64*4; idx += 128) {
        int r = idx >> 2, qu = idx & 3;
        int gq = q0 + r;
        uint4 v = make_uint4(0u, 0u, 0u, 0u);
        if (gq < SS) v = *(const uint4*)(qbase + (size_t)gq*HD + qu*8);
        *(uint4*)&Qsm[r*40 + qu*8] = v;
    }
    __syncthreads();

    u32 qa[2][4];
    {
        u32 qs = smem_u32(Qsm);
        int row = 16*w + (lane & 15);
        int cb = (lane >> 4) * 8;
        ldx4(qa[0], qs + (u32)((row*40 + cb) * 2));
        ldx4(qa[1], qs + (u32)((row*40 + cb + 16) * 2));
    }

    const u32 ks_base = smem_u32(Ksm);

    const int r0  = q0 + 16*w + g;
    const int r1i = r0 + 8;
    const float* mbb = mask + (size_t)b * SS * SS;
    const float* mr0 = (r0  < SS) ? mbb + (size_t)r0  * SS : (const float*)0;
    const float* mr1 = (r1i < SS) ? mbb + (size_t)r1i * SS : (const float*)0;

    float oacc[4][4];
    #pragma unroll
    for (int i = 0; i < 4; i++)
        #pragma unroll
        for (int c = 0; c < 4; c++) oacc[i][c] = 0.f;
    float rs0 = 0.f, rs1 = 0.f;

    // mask prefetch double-buffer
    float2 mbuf[2][4];
    auto do_pref = [&](int gjdx, float2* dst) {
        int nkt = gjdx >> 2, nj = gjdx & 3;
        int base = nkt*64 + nj*16;
        #pragma unroll
        for (int p = 0; p < 2; p++) {
            int gk = base + p*8 + 2*t4;
            bool v = gk < SS;
            dst[2*p]   = (v && mr0) ? *(const float2*)(mr0 + gk)
                                    : make_float2(-1e-6f, -1e-6f);
            dst[2*p+1] = (v && mr1) ? *(const float2*)(mr1 + gk)
                                    : make_float2(-1e-6f, -1e-6f);
        }
    };
    do_pref(0, mbuf[0]);

    // K tile load/store helpers
    const int kkr = t & 63, kpart = t >> 6;           // row, dim-half
    auto ldK = [&](int kt, uint4 &a0, uint4 &a1) {
        int gk = kt*64 + kkr;
        a0 = make_uint4(0u,0u,0u,0u); a1 = make_uint4(0u,0u,0u,0u);
        if (gk < SS) {
            a0 = *(const uint4*)(kbase + (size_t)gk*HD + kpart*16);
            a1 = *(const uint4*)(kbase + (size_t)gk*HD + kpart*16 + 8);
        }
    };
    auto stK = [&](int buf, uint4 a0, uint4 a1) {
        *(uint4*)&Ksm[buf*64*40 + kkr*40 + kpart*16]     = a0;
        *(uint4*)&Ksm[buf*64*40 + kkr*40 + kpart*16 + 8] = a1;
    };

    {
        uint4 p0, p1;
        ldK(0, p0, p1);
        stK(0, p0, p1);
    }
    __syncthreads();

    for (int kt = 0; kt < NKT2; kt++) {
        const u32 ks = ks_base + (u32)((kt & 1) * 64*40*2);
        const bool more = (kt + 1 < NKT2);
        uint4 n0v, n1v;
        if (more) ldK(kt + 1, n0v, n1v);

        #pragma unroll
        for (int j = 0; j < 4; j++) {
            const float2* mc = mbuf[j & 1];
            // ---- QK ----
            float sc[2][4];
            #pragma unroll
            for (int p = 0; p < 2; p++) {
                #pragma unroll
                for (int c = 0; c < 4; c++) sc[p][c] = 0.f;
                int nt = 2*j + p;
                u32 br[4];
                ldx4(br, ks + (u32)(((nt*8 + (lane & 7))*40 + ((lane>>3)&3)*8) * 2));
                mma_h(sc[p], qa[0], br[0], br[1]);
                mma_h(sc[p], qa[1], br[2], br[3]);
            }
            // prefetch next chunk's mask
            {
                int gn = kt*4 + j + 1;
                if (gn < NKT2*4) do_pref(gn, mbuf[(j+1) & 1]);
            }
            // ---- epilogue ----
            u32 wh[4];
            #pragma unroll
            for (int p = 0; p < 2; p++) {
                float2 m0 = mc[2*p], m1 = mc[2*p+1];
                float w00 = (m0.x + 1e-6f) * __expf(sc[p][0]);
                float w01 = (m0.y + 1e-6f) * __expf(sc[p][1]);
                float w10 = (m1.x + 1e-6f) * __expf(sc[p][2]);
                float w11 = (m1.y + 1e-6f) * __expf(sc[p][3]);
                rs0 += w00 + w01;
                rs1 += w10 + w11;
                wh[2*p]   = pack_h2(w00, w01);
                wh[2*p+1] = pack_h2(w10, w11);
            }
            // ---- PV via trans-ldmatrix straight from K tile ----
            #pragma unroll
            for (int ip = 0; ip < 2; ip++) {
                u32 vr[4];
                ldx4t(vr, ks + (u32)(((16*j + ((lane>>3)&1)*8 + (lane & 7))*40
                                      + ((lane>>4)&1)*8 + ip*16) * 2));
                mma_h(oacc[2*ip],   wh, vr[0], vr[1]);
                mma_h(oacc[2*ip+1], wh, vr[2], vr[3]);
            }
        }

        if (more) stK((kt + 1) & 1, n0v, n1v);
        __syncthreads();
    }

    rs0 += __shfl_xor_sync(0xffffffffu, rs0, 1);
    rs0 += __shfl_xor_sync(0xffffffffu, rs0, 2);
    rs1 += __shfl_xor_sync(0xffffffffu, rs1, 1);
    rs1 += __shfl_xor_sync(0xffffffffu, rs1, 2);
    float inv0 = 1.0f / rs0;
    float inv1 = 1.0f / rs1;

    if (r0 < SS) {
        float* o = d_acc + ((size_t)b*SS + r0)*CC + h*HD + 2*t4;
        #pragma unroll
        for (int i = 0; i < 4; i++)
            *(float2*)(o + i*8) = make_float2(oacc[i][0]*inv0, oacc[i][1]*inv0);
    }
    if (r1i < SS) {
        float* o = d_acc + ((size_t)b*SS + r1i)*CC + h*HD + 2*t4;
        #pragma unroll
        for (int i = 0; i < 4; i++)
            *(float2*)(o + i*8) = make_float2(oacc[i][2]*inv1, oacc[i][3]*inv1);
    }
}

// ---------------------------------------------------------------------------
// Kernel 3: LEPE depthwise 5x5 conv + acc split to fp16 hi/lo.
// Grid: BB*SS blocks (rows < QN: convert only).
// ---------------------------------------------------------------------------
__global__ __launch_bounds__(256) void lepe_kernel(
    const float* __restrict__ lw, const float* __restrict__ lb)
{
    int blk = blockIdx.x;
    int b = blk / SS, srow = blk % SS;
    int c = threadIdx.x;
    size_t idx = ((size_t)b*SS + srow)*CC + c;
    float a = d_acc[idx];
    if (srow >= QN) {
        int p = srow - QN;
        int y = p / 56, x = p % 56;
        float l = lb[c];
        #pragma unroll
        for (int ky = 0; ky < 5; ky++) {
            int iy = y + ky - 2;
            if (iy < 0 || iy >= 56) continue;
            #pragma unroll
            for (int kx = 0; kx < 5; kx++) {
                int ix = x + kx - 2;
                if (ix < 0 || ix >= 56) continue;
                l += d_v[((size_t)b*SS + QN + iy*56 + ix)*CC + c] * lw[(ky*5 + kx)*CC + c];
            }
        }
        a += l;
    }
    __half h, lo; split_h(a, h, lo);
    d_acch[idx] = h;
    d_accl[idx] = lo;
}

// ---------------------------------------------------------------------------
// Kernel 4: output projection, split-fp16 HMMA (3-pass). 64x64 tiles.
// ---------------------------------------------------------------------------
__global__ __launch_bounds__(256) void out_kernel(
    const float* __restrict__ bo, float* __restrict__ out)
{
    __shared__ __align__(16) u16 Xh[64*40];
    __shared__ __align__(16) u16 Xl[64*40];
    __shared__ __align__(16) u16 Wh[64*40];
    __shared__ __align__(16) u16 Wl[64*40];

    const int m0 = blockIdx.x * 64;
    const int n0 = blockIdx.y * 64;
    const int t = threadIdx.x;
    const int w = t >> 5, lane = t & 31;
    const int g = lane >> 2, t4 = lane & 3;
    const int wr = w >> 1, wc = w & 1;

    float acc[4][4];
    #pragma unroll
    for (int i = 0; i < 4; i++)
        #pragma unroll
        for (int c = 0; c < 4; c++) acc[i][c] = 0.f;

    const u32 xb  = smem_u32(Xh), xlb = smem_u32(Xl);
    const u32 wb  = smem_u32(Wh), wlb = smem_u32(Wl);

    for (int kk = 0; kk < CC; kk += 32) {
        __syncthreads();
        {
            int r = t >> 2, c8 = (t & 3) * 8;
            int gm = m0 + r;
            uint4 a = make_uint4(0u,0u,0u,0u), bvv = make_uint4(0u,0u,0u,0u);
            if (gm < MTOT) {
                a   = *(const uint4*)&d_acch[(size_t)gm*CC + kk + c8];
                bvv = *(const uint4*)&d_accl[(size_t)gm*CC + kk + c8];
            }
            *(uint4*)&Xh[r*40 + c8] = a;
            *(uint4*)&Xl[r*40 + c8] = bvv;
            int wrow = n0 + r;
            *(uint4*)&Wh[r*40 + c8] = *(const uint4*)&d_woh[(size_t)wrow*CC + kk + c8];
            *(uint4*)&Wl[r*40 + c8] = *(const uint4*)&d_wol[(size_t)wrow*CC + kk + c8];
        }
        __syncthreads();

        u32 ax[2][4], al[2][4];
        #pragma unroll
        for (int ks = 0; ks < 2; ks++) {
            u32 aoff = (u32)(((16*wr + (lane & 15))*40 + ks*16 + ((lane>>4)&1)*8) * 2);
            ldx4(ax[ks], xb  + aoff);
            ldx4(al[ks], xlb + aoff);
        }
        #pragma unroll
        for (int ks = 0; ks < 2; ks++) {
            #pragma unroll
            for (int np = 0; np < 2; np++) {
                u32 boff = (u32)(((32*wc + np*16 + ((lane>>4)&1)*8 + (lane & 7))*40
                                  + ks*16 + ((lane>>3)&1)*8) * 2);
                u32 bh4[4], bl4[4];
                ldx4(bh4, wb  + boff);
                ldx4(bl4, wlb + boff);
                mma_h(acc[2*np],   ax[ks], bh4[0], bh4[1]);
                mma_h(acc[2*np],   ax[ks], bl4[0], bl4[1]);
                mma_h(acc[2*np],   al[ks], bh4[0], bh4[1]);
                mma_h(acc[2*np+1], ax[ks], bh4[2], bh4[3]);
                mma_h(acc[2*np+1], ax[ks], bl4[2], bl4[3]);
                mma_h(acc[2*np+1], al[ks], bh4[2], bh4[3]);
            }
        }
    }

    #pragma unroll
    for (int nt = 0; nt < 4; nt++) {
        int n = n0 + 32*wc + 8*nt + 2*t4;
        float b0v = bo[n], b1v = bo[n+1];
        #pragma unroll
        for (int rr = 0; rr < 2; rr++) {
            int gm = m0 + 16*wr + g + rr*8;
            if (gm >= MTOT) continue;
            *(float2*)&out[(size_t)gm*CC + n] =
                make_float2(acc[nt][2*rr] + b0v, acc[nt][2*rr+1] + b1v);
        }
    }
}

// ---------------------------------------------------------------------------
extern "C" void kernel_launch(void* const* d_in, const int* in_sizes, int n_in,
                              void* d_out, int out_size) {
    const float* x    = (const float*)d_in[0];
    const float* mask = (const float*)d_in[1];
    const float* wq   = (const float*)d_in[2];
    const float* bq   = (const float*)d_in[3];
    const float* wk   = (const float*)d_in[4];
    const float* bk   = (const float*)d_in[5];
    const float* wv   = (const float*)d_in[6];
    const float* bv   = (const float*)d_in[7];
    const float* lw   = (const float*)d_in[8];
    const float* lb   = (const float*)d_in[9];
    const float* wo   = (const float*)d_in[10];
    const float* bo   = (const float*)d_in[11];
    float* out = (float*)d_out;

    int cvt_blocks = (NX + 4*65536 + 255) / 256;
    cvt_kernel<<<cvt_blocks, 256>>>(x, wq, wk, wv, wo);
    dim3 g1(99, 12);
    qkv_kernel<<<g1, 256>>>(bq, bk, bv);
    dim3 g2(BB*HH, NQT64);
    attn_mma_kernel<<<g2, 128>>>(mask);
    lepe_kernel<<<BB*SS, 256>>>(lw, lb);
    dim3 g4(99, 4);
    out_kernel<<<g4, 256>>>(bo, out);
}

// round 6
// speedup vs baseline: 5.8318x; 1.1687x over previous
#include <cuda_runtime.h>
#include <cuda_fp16.h>
#include <cstdint>

#define BB 2
#define SS 3144
#define CC 256
#define HH 8
#define HD 32
#define QN 8
#define MTOT (BB*SS)            /* 6288 */
#define SCALE 0.1767766952966369f
#define NKT2 ((SS + 63) / 64)   /* 50 key tiles of 64 */
#define NQT64 ((SS + 63) / 64)  /* 50 query tiles of 64 */
#define NX (MTOT*CC)

typedef unsigned long long u64;
typedef unsigned int u32;
typedef unsigned short u16;

__device__ __align__(16) __half d_qh[BB*HH*SS*HD];  // head-major fp16
__device__ __align__(16) __half d_kh[BB*HH*SS*HD];  // pre-scaled by SCALE (K and V)
__device__ __align__(16) float  d_v[BB*SS*CC];
__device__ __align__(16) float  d_acc[BB*SS*CC];    // attention out (f32)
__device__ __align__(16) __half d_xh[NX];           // x split hi/lo
__device__ __align__(16) __half d_xl[NX];
__device__ __align__(16) __half d_wh[768*CC];       // [wq;wk;wv] split
__device__ __align__(16) __half d_wl[768*CC];
__device__ __align__(16) __half d_woh[CC*CC];       // wo split
__device__ __align__(16) __half d_wol[CC*CC];
__device__ __align__(16) __half d_acch[BB*SS*CC];   // acc(+lepe) split
__device__ __align__(16) __half d_accl[BB*SS*CC];

// ---------------- helpers ----------------
__device__ __forceinline__ u32 smem_u32(const void* p) {
    u32 a;
    asm("{ .reg .u64 t; cvta.to.shared.u64 t, %1; cvt.u32.u64 %0, t; }" : "=r"(a) : "l"(p));
    return a;
}
__device__ __forceinline__ u32 pack_h2(float lo, float hi) {
    u32 r; asm("cvt.rn.f16x2.f32 %0, %1, %2;" : "=r"(r) : "f"(hi), "f"(lo)); return r;
}
__device__ __forceinline__ void ldx4(u32* r, u32 saddr) {
    asm volatile("ldmatrix.sync.aligned.m8n8.x4.shared.b16 {%0,%1,%2,%3}, [%4];"
                 : "=r"(r[0]), "=r"(r[1]), "=r"(r[2]), "=r"(r[3]) : "r"(saddr));
}
__device__ __forceinline__ void ldx4t(u32* r, u32 saddr) {
    asm volatile("ldmatrix.sync.aligned.m8n8.x4.trans.shared.b16 {%0,%1,%2,%3}, [%4];"
                 : "=r"(r[0]), "=r"(r[1]), "=r"(r[2]), "=r"(r[3]) : "r"(saddr));
}
__device__ __forceinline__ void mma_h(float* c, const u32* a, u32 b0, u32 b1) {
    asm volatile("mma.sync.aligned.m16n8k16.row.col.f32.f16.f16.f32 "
                 "{%0,%1,%2,%3}, {%4,%5,%6,%7}, {%8,%9}, {%0,%1,%2,%3};"
                 : "+f"(c[0]), "+f"(c[1]), "+f"(c[2]), "+f"(c[3])
                 : "r"(a[0]), "r"(a[1]), "r"(a[2]), "r"(a[3]), "r"(b0), "r"(b1));
}
__device__ __forceinline__ void split_h(float v, __half &h, __half &l) {
    h = __float2half_rn(v);
    l = __float2half_rn(v - __half2float(h));
}

// ---------------------------------------------------------------------------
// Kernel 0: split x, [wq;wk;wv], wo into fp16 hi/lo
// ---------------------------------------------------------------------------
__global__ __launch_bounds__(256) void cvt_kernel(
    const float* __restrict__ x,
    const float* __restrict__ wq, const float* __restrict__ wk,
    const float* __restrict__ wv, const float* __restrict__ wo)
{
    int idx = blockIdx.x * 256 + threadIdx.x;
    if (idx < NX) {
        __half h, l; split_h(x[idx], h, l);
        d_xh[idx] = h; d_xl[idx] = l;
    } else {
        int j = idx - NX;                 // 0 .. 4*65536-1
        int sec = j >> 16, off = j & 65535;
        const float* src = (sec == 0) ? wq : (sec == 1) ? wk : (sec == 2) ? wv : wo;
        __half h, l; split_h(src[off], h, l);
        if (sec < 3) { d_wh[j] = h; d_wl[j] = l; }
        else         { d_woh[off] = h; d_wol[off] = l; }
    }
}

// ---------------------------------------------------------------------------
// Kernel 1: fused QKV projection, split-fp16 HMMA (3-pass). 64x64 tiles.
// ---------------------------------------------------------------------------
__global__ __launch_bounds__(256) void qkv_kernel(
    const float* __restrict__ bq, const float* __restrict__ bk,
    const float* __restrict__ bv)
{
    __shared__ __align__(16) u16 Xh[64*40];
    __shared__ __align__(16) u16 Xl[64*40];
    __shared__ __align__(16) u16 Wh[64*40];
    __shared__ __align__(16) u16 Wl[64*40];

    const int m0 = blockIdx.x * 64;
    const int n0 = blockIdx.y * 64;       // global 0..767
    const int t = threadIdx.x;
    const int w = t >> 5, lane = t & 31;
    const int g = lane >> 2, t4 = lane & 3;
    const int wr = w >> 1, wc = w & 1;
    const int sec = n0 >> 8;
    const int nbase = n0 & 255;

    float acc[4][4];
    #pragma unroll
    for (int i = 0; i < 4; i++)
        #pragma unroll
        for (int c = 0; c < 4; c++) acc[i][c] = 0.f;

    const u32 xb  = smem_u32(Xh), xlb = smem_u32(Xl);
    const u32 wb  = smem_u32(Wh), wlb = smem_u32(Wl);

    for (int kk = 0; kk < CC; kk += 32) {
        __syncthreads();
        {
            int r = t >> 2, c8 = (t & 3) * 8;
            int gm = m0 + r;
            uint4 a = make_uint4(0u,0u,0u,0u), b = make_uint4(0u,0u,0u,0u);
            if (gm < MTOT) {
                a = *(const uint4*)&d_xh[(size_t)gm*CC + kk + c8];
                b = *(const uint4*)&d_xl[(size_t)gm*CC + kk + c8];
            }
            *(uint4*)&Xh[r*40 + c8] = a;
            *(uint4*)&Xl[r*40 + c8] = b;
            int wrow = n0 + r;
            *(uint4*)&Wh[r*40 + c8] = *(const uint4*)&d_wh[(size_t)wrow*CC + kk + c8];
            *(uint4*)&Wl[r*40 + c8] = *(const uint4*)&d_wl[(size_t)wrow*CC + kk + c8];
        }
        __syncthreads();

        u32 ax[2][4], al[2][4];
        #pragma unroll
        for (int ks = 0; ks < 2; ks++) {
            u32 aoff = (u32)(((16*wr + (lane & 15))*40 + ks*16 + ((lane>>4)&1)*8) * 2);
            ldx4(ax[ks], xb  + aoff);
            ldx4(al[ks], xlb + aoff);
        }
        #pragma unroll
        for (int ks = 0; ks < 2; ks++) {
            #pragma unroll
            for (int np = 0; np < 2; np++) {
                u32 boff = (u32)(((32*wc + np*16 + ((lane>>4)&1)*8 + (lane & 7))*40
                                  + ks*16 + ((lane>>3)&1)*8) * 2);
                u32 bh4[4], bl4[4];
                ldx4(bh4, wb  + boff);
                ldx4(bl4, wlb + boff);
                mma_h(acc[2*np],   ax[ks], bh4[0], bh4[1]);
                mma_h(acc[2*np],   ax[ks], bl4[0], bl4[1]);
                mma_h(acc[2*np],   al[ks], bh4[0], bh4[1]);
                mma_h(acc[2*np+1], ax[ks], bh4[2], bh4[3]);
                mma_h(acc[2*np+1], ax[ks], bl4[2], bl4[3]);
                mma_h(acc[2*np+1], al[ks], bh4[2], bh4[3]);
            }
        }
    }

    const float* bsec = (sec == 0) ? bq : (sec == 1) ? bk : bv;
    #pragma unroll
    for (int nt = 0; nt < 4; nt++) {
        int ct = 32*wc + 8*nt + 2*t4;
        int c = nbase + ct;
        float b0v = bsec[c], b1v = bsec[c+1];
        #pragma unroll
        for (int rr = 0; rr < 2; rr++) {
            int gm = m0 + 16*wr + g + rr*8;
            if (gm >= MTOT) continue;
            float v0 = acc[nt][2*rr]   + b0v;
            float v1 = acc[nt][2*rr+1] + b1v;
            int b = gm / SS, srow = gm % SS;
            if (sec == 0) {
                *(__half2*)&d_qh[(((size_t)b*HH + (c>>5))*SS + srow)*HD + (c&31)] =
                    __floats2half2_rn(v0, v1);
            } else if (sec == 1) {
                *(__half2*)&d_kh[(((size_t)b*HH + (c>>5))*SS + srow)*HD + (c&31)] =
                    __floats2half2_rn(v0*SCALE, v1*SCALE);
            } else {
                *(float2*)&d_v[(size_t)gm*CC + c] = make_float2(v0, v1);
            }
        }
    }
}

// ---------------------------------------------------------------------------
// Kernel 2: fp16 mma.sync attention — 2 HEADS PER BLOCK (mask L1/L2 reuse).
// Block: 256 thr (8 warps = 2 head-groups of 4), 64 q rows. 50 key tiles of 64.
// Warp w: head hp = w>>2, q-row group w4 = w&3.
// ---------------------------------------------------------------------------
__global__ void __launch_bounds__(256, 3) attn_mma_kernel(const float* __restrict__ mask)
{
    __shared__ __align__(16) u16 Qsm[2*64*40];     // 10240 B (2 heads)
    __shared__ __align__(16) u16 Ksm[2*2*64*40];   // 20480 B (2 heads x double buf)

    const int t = threadIdx.x;
    const int w = t >> 5, lane = t & 31;
    const int g = lane >> 2, t4 = lane & 3;
    const int hp = w >> 2, w4 = w & 3;
    const int bhp = blockIdx.x;
    const int b = bhp >> 2, hpair = bhp & 3;
    const int h = hpair*2 + hp;
    const int q0 = blockIdx.y * 64;

    const __half* qbase = d_qh + (((size_t)b*HH + h) * SS) * HD;
    const __half* kbase = d_kh + (((size_t)b*HH + h) * SS) * HD;

    // ---- stage Q tiles for both heads ----
    {
        int hld = t >> 7, r = (t >> 1) & 63, part = t & 1;
        const __half* qb2 = d_qh + (((size_t)b*HH + hpair*2 + hld) * SS) * HD;
        int gq = q0 + r;
        uint4 a0 = make_uint4(0u,0u,0u,0u), a1 = make_uint4(0u,0u,0u,0u);
        if (gq < SS) {
            a0 = *(const uint4*)(qb2 + (size_t)gq*HD + part*16);
            a1 = *(const uint4*)(qb2 + (size_t)gq*HD + part*16 + 8);
        }
        *(uint4*)&Qsm[hld*64*40 + r*40 + part*16]     = a0;
        *(uint4*)&Qsm[hld*64*40 + r*40 + part*16 + 8] = a1;
    }
    __syncthreads();

    u32 qa[2][4];
    {
        u32 qs = smem_u32(Qsm) + (u32)(hp*64*40*2);
        int row = 16*w4 + (lane & 15);
        int cb = (lane >> 4) * 8;
        ldx4(qa[0], qs + (u32)((row*40 + cb) * 2));
        ldx4(qa[1], qs + (u32)((row*40 + cb + 16) * 2));
    }

    const u32 ks_base = smem_u32(Ksm);

    const int r0  = q0 + 16*w4 + g;
    const int r1i = r0 + 8;
    const float* mbb = mask + (size_t)b * SS * SS;
    const float* mr0 = (r0  < SS) ? mbb + (size_t)r0  * SS : (const float*)0;
    const float* mr1 = (r1i < SS) ? mbb + (size_t)r1i * SS : (const float*)0;

    float oacc[4][4];
    #pragma unroll
    for (int i = 0; i < 4; i++)
        #pragma unroll
        for (int c = 0; c < 4; c++) oacc[i][c] = 0.f;
    float rs0 = 0.f, rs1 = 0.f;

    // mask prefetch double-buffer
    float2 mbuf[2][4];
    auto do_pref = [&](int gjdx, float2* dst) {
        int nkt = gjdx >> 2, nj = gjdx & 3;
        int base = nkt*64 + nj*16;
        #pragma unroll
        for (int p = 0; p < 2; p++) {
            int gk = base + p*8 + 2*t4;
            bool v = gk < SS;
            dst[2*p]   = (v && mr0) ? *(const float2*)(mr0 + gk)
                                    : make_float2(-1e-6f, -1e-6f);
            dst[2*p+1] = (v && mr1) ? *(const float2*)(mr1 + gk)
                                    : make_float2(-1e-6f, -1e-6f);
        }
    };
    do_pref(0, mbuf[0]);

    // K tile load/store: 256 thr cover 2 heads x 64 rows x 32 halves
    const int khld = t >> 7, kkr = (t >> 1) & 63, kpart = t & 1;
    const __half* kldb = d_kh + (((size_t)b*HH + hpair*2 + khld) * SS) * HD;
    auto ldK = [&](int kt, uint4 &a0, uint4 &a1) {
        int gk = kt*64 + kkr;
        a0 = make_uint4(0u,0u,0u,0u); a1 = make_uint4(0u,0u,0u,0u);
        if (gk < SS) {
            a0 = *(const uint4*)(kldb + (size_t)gk*HD + kpart*16);
            a1 = *(const uint4*)(kldb + (size_t)gk*HD + kpart*16 + 8);
        }
    };
    auto stK = [&](int buf, uint4 a0, uint4 a1) {
        int base = (khld*2 + buf)*64*40;
        *(uint4*)&Ksm[base + kkr*40 + kpart*16]     = a0;
        *(uint4*)&Ksm[base + kkr*40 + kpart*16 + 8] = a1;
    };

    {
        uint4 p0, p1;
        ldK(0, p0, p1);
        stK(0, p0, p1);
    }
    __syncthreads();

    for (int kt = 0; kt < NKT2; kt++) {
        const u32 ks = ks_base + (u32)(((hp*2 + (kt & 1)) * 64*40) * 2);
        const bool more = (kt + 1 < NKT2);
        uint4 n0v, n1v;
        if (more) ldK(kt + 1, n0v, n1v);

        #pragma unroll
        for (int j = 0; j < 4; j++) {
            const float2* mc = mbuf[j & 1];
            // ---- QK ----
            float sc[2][4];
            #pragma unroll
            for (int p = 0; p < 2; p++) {
                #pragma unroll
                for (int c = 0; c < 4; c++) sc[p][c] = 0.f;
                int nt = 2*j + p;
                u32 br[4];
                ldx4(br, ks + (u32)(((nt*8 + (lane & 7))*40 + ((lane>>3)&3)*8) * 2));
                mma_h(sc[p], qa[0], br[0], br[1]);
                mma_h(sc[p], qa[1], br[2], br[3]);
            }
            // prefetch next chunk's mask
            {
                int gn = kt*4 + j + 1;
                if (gn < NKT2*4) do_pref(gn, mbuf[(j+1) & 1]);
            }
            // ---- epilogue ----
            u32 wh[4];
            #pragma unroll
            for (int p = 0; p < 2; p++) {
                float2 m0 = mc[2*p], m1 = mc[2*p+1];
                float w00 = (m0.x + 1e-6f) * __expf(sc[p][0]);
                float w01 = (m0.y + 1e-6f) * __expf(sc[p][1]);
                float w10 = (m1.x + 1e-6f) * __expf(sc[p][2]);
                float w11 = (m1.y + 1e-6f) * __expf(sc[p][3]);
                rs0 += w00 + w01;
                rs1 += w10 + w11;
                wh[2*p]   = pack_h2(w00, w01);
                wh[2*p+1] = pack_h2(w10, w11);
            }
            // ---- PV via trans-ldmatrix straight from K tile ----
            #pragma unroll
            for (int ip = 0; ip < 2; ip++) {
                u32 vr[4];
                ldx4t(vr, ks + (u32)(((16*j + ((lane>>3)&1)*8 + (lane & 7))*40
                                      + ((lane>>4)&1)*8 + ip*16) * 2));
                mma_h(oacc[2*ip],   wh, vr[0], vr[1]);
                mma_h(oacc[2*ip+1], wh, vr[2], vr[3]);
            }
        }

        if (more) stK((kt + 1) & 1, n0v, n1v);
        __syncthreads();
    }

    rs0 += __shfl_xor_sync(0xffffffffu, rs0, 1);
    rs0 += __shfl_xor_sync(0xffffffffu, rs0, 2);
    rs1 += __shfl_xor_sync(0xffffffffu, rs1, 1);
    rs1 += __shfl_xor_sync(0xffffffffu, rs1, 2);
    float inv0 = 1.0f / rs0;
    float inv1 = 1.0f / rs1;

    if (r0 < SS) {
        float* o = d_acc + ((size_t)b*SS + r0)*CC + h*HD + 2*t4;
        #pragma unroll
        for (int i = 0; i < 4; i++)
            *(float2*)(o + i*8) = make_float2(oacc[i][0]*inv0, oacc[i][1]*inv0);
    }
    if (r1i < SS) {
        float* o = d_acc + ((size_t)b*SS + r1i)*CC + h*HD + 2*t4;
        #pragma unroll
        for (int i = 0; i < 4; i++)
            *(float2*)(o + i*8) = make_float2(oacc[i][2]*inv1, oacc[i][3]*inv1);
    }
}

// ---------------------------------------------------------------------------
// Kernel 3: LEPE depthwise 5x5 conv + acc split to fp16 hi/lo.
// ---------------------------------------------------------------------------
__global__ __launch_bounds__(256) void lepe_kernel(
    const float* __restrict__ lw, const float* __restrict__ lb)
{
    int blk = blockIdx.x;
    int b = blk / SS, srow = blk % SS;
    int c = threadIdx.x;
    size_t idx = ((size_t)b*SS + srow)*CC + c;
    float a = d_acc[idx];
    if (srow >= QN) {
        int p = srow - QN;
        int y = p / 56, x = p % 56;
        float l = lb[c];
        #pragma unroll
        for (int ky = 0; ky < 5; ky++) {
            int iy = y + ky - 2;
            if (iy < 0 || iy >= 56) continue;
            #pragma unroll
            for (int kx = 0; kx < 5; kx++) {
                int ix = x + kx - 2;
                if (ix < 0 || ix >= 56) continue;
                l += d_v[((size_t)b*SS + QN + iy*56 + ix)*CC + c] * lw[(ky*5 + kx)*CC + c];
            }
        }
        a += l;
    }
    __half h, lo; split_h(a, h, lo);
    d_acch[idx] = h;
    d_accl[idx] = lo;
}

// ---------------------------------------------------------------------------
// Kernel 4: output projection, split-fp16 HMMA (3-pass). 64x64 tiles.
// ---------------------------------------------------------------------------
__global__ __launch_bounds__(256) void out_kernel(
    const float* __restrict__ bo, float* __restrict__ out)
{
    __shared__ __align__(16) u16 Xh[64*40];
    __shared__ __align__(16) u16 Xl[64*40];
    __shared__ __align__(16) u16 Wh[64*40];
    __shared__ __align__(16) u16 Wl[64*40];

    const int m0 = blockIdx.x * 64;
    const int n0 = blockIdx.y * 64;
    const int t = threadIdx.x;
    const int w = t >> 5, lane = t & 31;
    const int g = lane >> 2, t4 = lane & 3;
    const int wr = w >> 1, wc = w & 1;

    float acc[4][4];
    #pragma unroll
    for (int i = 0; i < 4; i++)
        #pragma unroll
        for (int c = 0; c < 4; c++) acc[i][c] = 0.f;

    const u32 xb  = smem_u32(Xh), xlb = smem_u32(Xl);
    const u32 wb  = smem_u32(Wh), wlb = smem_u32(Wl);

    for (int kk = 0; kk < CC; kk += 32) {
        __syncthreads();
        {
            int r = t >> 2, c8 = (t & 3) * 8;
            int gm = m0 + r;
            uint4 a = make_uint4(0u,0u,0u,0u), bvv = make_uint4(0u,0u,0u,0u);
            if (gm < MTOT) {
                a   = *(const uint4*)&d_acch[(size_t)gm*CC + kk + c8];
                bvv = *(const uint4*)&d_accl[(size_t)gm*CC + kk + c8];
            }
            *(uint4*)&Xh[r*40 + c8] = a;
            *(uint4*)&Xl[r*40 + c8] = bvv;
            int wrow = n0 + r;
            *(uint4*)&Wh[r*40 + c8] = *(const uint4*)&d_woh[(size_t)wrow*CC + kk + c8];
            *(uint4*)&Wl[r*40 + c8] = *(const uint4*)&d_wol[(size_t)wrow*CC + kk + c8];
        }
        __syncthreads();

        u32 ax[2][4], al[2][4];
        #pragma unroll
        for (int ks = 0; ks < 2; ks++) {
            u32 aoff = (u32)(((16*wr + (lane & 15))*40 + ks*16 + ((lane>>4)&1)*8) * 2);
            ldx4(ax[ks], xb  + aoff);
            ldx4(al[ks], xlb + aoff);
        }
        #pragma unroll
        for (int ks = 0; ks < 2; ks++) {
            #pragma unroll
            for (int np = 0; np < 2; np++) {
                u32 boff = (u32)(((32*wc + np*16 + ((lane>>4)&1)*8 + (lane & 7))*40
                                  + ks*16 + ((lane>>3)&1)*8) * 2);
                u32 bh4[4], bl4[4];
                ldx4(bh4, wb  + boff);
                ldx4(bl4, wlb + boff);
                mma_h(acc[2*np],   ax[ks], bh4[0], bh4[1]);
                mma_h(acc[2*np],   ax[ks], bl4[0], bl4[1]);
                mma_h(acc[2*np],   al[ks], bh4[0], bh4[1]);
                mma_h(acc[2*np+1], ax[ks], bh4[2], bh4[3]);
                mma_h(acc[2*np+1], ax[ks], bl4[2], bl4[3]);
                mma_h(acc[2*np+1], al[ks], bh4[2], bh4[3]);
            }
        }
    }

    #pragma unroll
    for (int nt = 0; nt < 4; nt++) {
        int n = n0 + 32*wc + 8*nt + 2*t4;
        float b0v = bo[n], b1v = bo[n+1];
        #pragma unroll
        for (int rr = 0; rr < 2; rr++) {
            int gm = m0 + 16*wr + g + rr*8;
            if (gm >= MTOT) continue;
            *(float2*)&out[(size_t)gm*CC + n] =
                make_float2(acc[nt][2*rr] + b0v, acc[nt][2*rr+1] + b1v);
        }
    }
}

// ---------------------------------------------------------------------------
extern "C" void kernel_launch(void* const* d_in, const int* in_sizes, int n_in,
                              void* d_out, int out_size) {
    const float* x    = (const float*)d_in[0];
    const float* mask = (const float*)d_in[1];
    const float* wq   = (const float*)d_in[2];
    const float* bq   = (const float*)d_in[3];
    const float* wk   = (const float*)d_in[4];
    const float* bk   = (const float*)d_in[5];
    const float* wv   = (const float*)d_in[6];
    const float* bv   = (const float*)d_in[7];
    const float* lw   = (const float*)d_in[8];
    const float* lb   = (const float*)d_in[9];
    const float* wo   = (const float*)d_in[10];
    const float* bo   = (const float*)d_in[11];
    float* out = (float*)d_out;

    int cvt_blocks = (NX + 4*65536 + 255) / 256;
    cvt_kernel<<<cvt_blocks, 256>>>(x, wq, wk, wv, wo);
    dim3 g1(99, 12);
    qkv_kernel<<<g1, 256>>>(bq, bk, bv);
    dim3 g2(BB*4, NQT64);
    attn_mma_kernel<<<g2, 256>>>(mask);
    lepe_kernel<<<BB*SS, 256>>>(lw, lb);
    dim3 g4(99, 4);
    out_kernel<<<g4, 256>>>(bo, out);
}

// round 7
// speedup vs baseline: 6.2071x; 1.0643x over previous
#include <cuda_runtime.h>
#include <cuda_fp16.h>
#include <cstdint>

#define BB 2
#define SS 3144
#define CC 256
#define HH 8
#define HD 32
#define QN 8
#define MTOT (BB*SS)            /* 6288 */
#define SCALE 0.1767766952966369f
#define NKT2 ((SS + 63) / 64)   /* 50 key tiles of 64 */
#define NQT64 ((SS + 63) / 64)  /* 50 query tiles of 64 */

typedef unsigned long long u64;
typedef unsigned int u32;
typedef unsigned short u16;

__device__ __align__(16) __half d_qh[BB*HH*SS*HD];  // head-major fp16
__device__ __align__(16) __half d_kh[BB*HH*SS*HD];  // pre-scaled by SCALE (K and V)
__device__ __align__(16) float  d_v[BB*SS*CC];
__device__ __align__(16) float  d_acc[BB*SS*CC];    // attention out (f32)
__device__ __align__(16) __half d_wh[768*CC];       // [wq;wk;wv] split
__device__ __align__(16) __half d_wl[768*CC];
__device__ __align__(16) __half d_woh[CC*CC];       // wo split
__device__ __align__(16) __half d_wol[CC*CC];
__device__ __align__(16) __half d_acch[BB*SS*CC];   // acc(+lepe) split
__device__ __align__(16) __half d_accl[BB*SS*CC];

// ---------------- helpers ----------------
__device__ __forceinline__ u32 smem_u32(const void* p) {
    u32 a;
    asm("{ .reg .u64 t; cvta.to.shared.u64 t, %1; cvt.u32.u64 %0, t; }" : "=r"(a) : "l"(p));
    return a;
}
__device__ __forceinline__ u32 pack_h2(float lo, float hi) {
    u32 r; asm("cvt.rn.f16x2.f32 %0, %1, %2;" : "=r"(r) : "f"(hi), "f"(lo)); return r;
}
__device__ __forceinline__ void ldx4(u32* r, u32 saddr) {
    asm volatile("ldmatrix.sync.aligned.m8n8.x4.shared.b16 {%0,%1,%2,%3}, [%4];"
                 : "=r"(r[0]), "=r"(r[1]), "=r"(r[2]), "=r"(r[3]) : "r"(saddr));
}
__device__ __forceinline__ void ldx4t(u32* r, u32 saddr) {
    asm volatile("ldmatrix.sync.aligned.m8n8.x4.trans.shared.b16 {%0,%1,%2,%3}, [%4];"
                 : "=r"(r[0]), "=r"(r[1]), "=r"(r[2]), "=r"(r[3]) : "r"(saddr));
}
__device__ __forceinline__ void mma_h(float* c, const u32* a, u32 b0, u32 b1) {
    asm volatile("mma.sync.aligned.m16n8k16.row.col.f32.f16.f16.f32 "
                 "{%0,%1,%2,%3}, {%4,%5,%6,%7}, {%8,%9}, {%0,%1,%2,%3};"
                 : "+f"(c[0]), "+f"(c[1]), "+f"(c[2]), "+f"(c[3])
                 : "r"(a[0]), "r"(a[1]), "r"(a[2]), "r"(a[3]), "r"(b0), "r"(b1));
}
__device__ __forceinline__ void split_h(float v, __half &h, __half &l) {
    h = __float2half_rn(v);
    l = __float2half_rn(v - __half2float(h));
}

// ---------------------------------------------------------------------------
// Kernel 0: split [wq;wk;wv], wo into fp16 hi/lo (weights only)
// ---------------------------------------------------------------------------
__global__ __launch_bounds__(256) void cvt_kernel(
    const float* __restrict__ wq, const float* __restrict__ wk,
    const float* __restrict__ wv, const float* __restrict__ wo)
{
    int j = blockIdx.x * 256 + threadIdx.x;      // 0 .. 4*65536-1
    int sec = j >> 16, off = j & 65535;
    const float* src = (sec == 0) ? wq : (sec == 1) ? wk : (sec == 2) ? wv : wo;
    __half h, l; split_h(src[off], h, l);
    if (sec < 3) { d_wh[j] = h; d_wl[j] = l; }
    else         { d_woh[off] = h; d_wol[off] = l; }
}

// ---------------------------------------------------------------------------
// Kernel 1: fused QKV projection. x split in-kernel.
// q,k sections: single-pass fp16 HMMA. v section: 3-pass split-fp16.
// ---------------------------------------------------------------------------
__global__ __launch_bounds__(256) void qkv_kernel(
    const float* __restrict__ x,
    const float* __restrict__ bq, const float* __restrict__ bk,
    const float* __restrict__ bv)
{
    __shared__ __align__(16) u16 Xh[64*40];
    __shared__ __align__(16) u16 Xl[64*40];
    __shared__ __align__(16) u16 Wh[64*40];
    __shared__ __align__(16) u16 Wl[64*40];

    const int m0 = blockIdx.x * 64;
    const int n0 = blockIdx.y * 64;       // global 0..767
    const int t = threadIdx.x;
    const int w = t >> 5, lane = t & 31;
    const int g = lane >> 2, t4 = lane & 3;
    const int wr = w >> 1, wc = w & 1;
    const int sec = n0 >> 8;
    const int nbase = n0 & 255;
    const bool isv = (sec == 2);

    float acc[4][4];
    #pragma unroll
    for (int i = 0; i < 4; i++)
        #pragma unroll
        for (int c = 0; c < 4; c++) acc[i][c] = 0.f;

    const u32 xb  = smem_u32(Xh), xlb = smem_u32(Xl);
    const u32 wb  = smem_u32(Wh), wlb = smem_u32(Wl);

    for (int kk = 0; kk < CC; kk += 32) {
        __syncthreads();
        {
            int r = t >> 2, c8 = (t & 3) * 8;
            int gm = m0 + r;
            float4 f0 = make_float4(0.f,0.f,0.f,0.f), f1 = f0;
            if (gm < MTOT) {
                f0 = *(const float4*)(x + (size_t)gm*CC + kk + c8);
                f1 = *(const float4*)(x + (size_t)gm*CC + kk + c8 + 4);
            }
            float vv[8] = {f0.x,f0.y,f0.z,f0.w,f1.x,f1.y,f1.z,f1.w};
            __half hh[8], ll[8];
            #pragma unroll
            for (int i = 0; i < 8; i++) split_h(vv[i], hh[i], ll[i]);
            *(uint4*)&Xh[r*40 + c8] = *(uint4*)hh;
            if (isv) *(uint4*)&Xl[r*40 + c8] = *(uint4*)ll;
            int wrow = n0 + r;
            *(uint4*)&Wh[r*40 + c8] = *(const uint4*)&d_wh[(size_t)wrow*CC + kk + c8];
            if (isv) *(uint4*)&Wl[r*40 + c8] = *(const uint4*)&d_wl[(size_t)wrow*CC + kk + c8];
        }
        __syncthreads();

        u32 ax[2][4], al[2][4];
        #pragma unroll
        for (int ks = 0; ks < 2; ks++) {
            u32 aoff = (u32)(((16*wr + (lane & 15))*40 + ks*16 + ((lane>>4)&1)*8) * 2);
            ldx4(ax[ks], xb + aoff);
            if (isv) ldx4(al[ks], xlb + aoff);
        }
        #pragma unroll
        for (int ks = 0; ks < 2; ks++) {
            #pragma unroll
            for (int np = 0; np < 2; np++) {
                u32 boff = (u32)(((32*wc + np*16 + ((lane>>4)&1)*8 + (lane & 7))*40
                                  + ks*16 + ((lane>>3)&1)*8) * 2);
                u32 bh4[4];
                ldx4(bh4, wb + boff);
                mma_h(acc[2*np],   ax[ks], bh4[0], bh4[1]);
                mma_h(acc[2*np+1], ax[ks], bh4[2], bh4[3]);
                if (isv) {
                    u32 bl4[4];
                    ldx4(bl4, wlb + boff);
                    mma_h(acc[2*np],   ax[ks], bl4[0], bl4[1]);
                    mma_h(acc[2*np],   al[ks], bh4[0], bh4[1]);
                    mma_h(acc[2*np+1], ax[ks], bl4[2], bl4[3]);
                    mma_h(acc[2*np+1], al[ks], bh4[2], bh4[3]);
                }
            }
        }
    }

    const float* bsec = (sec == 0) ? bq : (sec == 1) ? bk : bv;
    #pragma unroll
    for (int nt = 0; nt < 4; nt++) {
        int ct = 32*wc + 8*nt + 2*t4;
        int c = nbase + ct;
        float b0v = bsec[c], b1v = bsec[c+1];
        #pragma unroll
        for (int rr = 0; rr < 2; rr++) {
            int gm = m0 + 16*wr + g + rr*8;
            if (gm >= MTOT) continue;
            float v0 = acc[nt][2*rr]   + b0v;
            float v1 = acc[nt][2*rr+1] + b1v;
            int b = gm / SS, srow = gm % SS;
            if (sec == 0) {
                *(__half2*)&d_qh[(((size_t)b*HH + (c>>5))*SS + srow)*HD + (c&31)] =
                    __floats2half2_rn(v0, v1);
            } else if (sec == 1) {
                *(__half2*)&d_kh[(((size_t)b*HH + (c>>5))*SS + srow)*HD + (c&31)] =
                    __floats2half2_rn(v0*SCALE, v1*SCALE);
            } else {
                *(float2*)&d_v[(size_t)gm*CC + c] = make_float2(v0, v1);
            }
        }
    }
}

// ---------------------------------------------------------------------------
// Kernel 2: fp16 mma.sync attention — 2 heads per block (mask L1/L2 reuse).
// Block: 256 thr (8 warps = 2 head-groups of 4), 64 q rows. 50 key tiles of 64.
// ---------------------------------------------------------------------------
__global__ void __launch_bounds__(256, 3) attn_mma_kernel(const float* __restrict__ mask)
{
    __shared__ __align__(16) u16 Qsm[2*64*40];     // 10240 B (2 heads)
    __shared__ __align__(16) u16 Ksm[2*2*64*40];   // 20480 B (2 heads x double buf)

    const int t = threadIdx.x;
    const int w = t >> 5, lane = t & 31;
    const int g = lane >> 2, t4 = lane & 3;
    const int hp = w >> 2, w4 = w & 3;
    const int bhp = blockIdx.x;
    const int b = bhp >> 2, hpair = bhp & 3;
    const int h = hpair*2 + hp;
    const int q0 = blockIdx.y * 64;

    // ---- stage Q tiles for both heads ----
    {
        int hld = t >> 7, r = (t >> 1) & 63, part = t & 1;
        const __half* qb2 = d_qh + (((size_t)b*HH + hpair*2 + hld) * SS) * HD;
        int gq = q0 + r;
        uint4 a0 = make_uint4(0u,0u,0u,0u), a1 = make_uint4(0u,0u,0u,0u);
        if (gq < SS) {
            a0 = *(const uint4*)(qb2 + (size_t)gq*HD + part*16);
            a1 = *(const uint4*)(qb2 + (size_t)gq*HD + part*16 + 8);
        }
        *(uint4*)&Qsm[hld*64*40 + r*40 + part*16]     = a0;
        *(uint4*)&Qsm[hld*64*40 + r*40 + part*16 + 8] = a1;
    }
    __syncthreads();

    u32 qa[2][4];
    {
        u32 qs = smem_u32(Qsm) + (u32)(hp*64*40*2);
        int row = 16*w4 + (lane & 15);
        int cb = (lane >> 4) * 8;
        ldx4(qa[0], qs + (u32)((row*40 + cb) * 2));
        ldx4(qa[1], qs + (u32)((row*40 + cb + 16) * 2));
    }

    const u32 ks_base = smem_u32(Ksm);

    const int r0  = q0 + 16*w4 + g;
    const int r1i = r0 + 8;
    const float* mbb = mask + (size_t)b * SS * SS;
    const float* mr0 = (r0  < SS) ? mbb + (size_t)r0  * SS : (const float*)0;
    const float* mr1 = (r1i < SS) ? mbb + (size_t)r1i * SS : (const float*)0;

    float oacc[4][4];
    #pragma unroll
    for (int i = 0; i < 4; i++)
        #pragma unroll
        for (int c = 0; c < 4; c++) oacc[i][c] = 0.f;
    float rs0 = 0.f, rs1 = 0.f;

    // mask prefetch double-buffer
    float2 mbuf[2][4];
    auto do_pref = [&](int gjdx, float2* dst) {
        int nkt = gjdx >> 2, nj = gjdx & 3;
        int base = nkt*64 + nj*16;
        #pragma unroll
        for (int p = 0; p < 2; p++) {
            int gk = base + p*8 + 2*t4;
            bool v = gk < SS;
            dst[2*p]   = (v && mr0) ? *(const float2*)(mr0 + gk)
                                    : make_float2(-1e-6f, -1e-6f);
            dst[2*p+1] = (v && mr1) ? *(const float2*)(mr1 + gk)
                                    : make_float2(-1e-6f, -1e-6f);
        }
    };
    do_pref(0, mbuf[0]);

    // K tile load/store: 256 thr cover 2 heads x 64 rows x 32 halves
    const int khld = t >> 7, kkr = (t >> 1) & 63, kpart = t & 1;
    const __half* kldb = d_kh + (((size_t)b*HH + hpair*2 + khld) * SS) * HD;
    auto ldK = [&](int kt, uint4 &a0, uint4 &a1) {
        int gk = kt*64 + kkr;
        a0 = make_uint4(0u,0u,0u,0u); a1 = make_uint4(0u,0u,0u,0u);
        if (gk < SS) {
            a0 = *(const uint4*)(kldb + (size_t)gk*HD + kpart*16);
            a1 = *(const uint4*)(kldb + (size_t)gk*HD + kpart*16 + 8);
        }
    };
    auto stK = [&](int buf, uint4 a0, uint4 a1) {
        int base = (khld*2 + buf)*64*40;
        *(uint4*)&Ksm[base + kkr*40 + kpart*16]     = a0;
        *(uint4*)&Ksm[base + kkr*40 + kpart*16 + 8] = a1;
    };

    {
        uint4 p0, p1;
        ldK(0, p0, p1);
        stK(0, p0, p1);
    }
    __syncthreads();

    for (int kt = 0; kt < NKT2; kt++) {
        const u32 ks = ks_base + (u32)(((hp*2 + (kt & 1)) * 64*40) * 2);
        const bool more = (kt + 1 < NKT2);
        uint4 n0v, n1v;
        if (more) ldK(kt + 1, n0v, n1v);

        #pragma unroll
        for (int j = 0; j < 4; j++) {
            const float2* mc = mbuf[j & 1];
            // ---- QK ----
            float sc[2][4];
            #pragma unroll
            for (int p = 0; p < 2; p++) {
                #pragma unroll
                for (int c = 0; c < 4; c++) sc[p][c] = 0.f;
                int nt = 2*j + p;
                u32 br[4];
                ldx4(br, ks + (u32)(((nt*8 + (lane & 7))*40 + ((lane>>3)&3)*8) * 2));
                mma_h(sc[p], qa[0], br[0], br[1]);
                mma_h(sc[p], qa[1], br[2], br[3]);
            }
            // prefetch next chunk's mask
            {
                int gn = kt*4 + j + 1;
                if (gn < NKT2*4) do_pref(gn, mbuf[(j+1) & 1]);
            }
            // ---- epilogue ----
            u32 wh[4];
            #pragma unroll
            for (int p = 0; p < 2; p++) {
                float2 m0 = mc[2*p], m1 = mc[2*p+1];
                float w00 = (m0.x + 1e-6f) * __expf(sc[p][0]);
                float w01 = (m0.y + 1e-6f) * __expf(sc[p][1]);
                float w10 = (m1.x + 1e-6f) * __expf(sc[p][2]);
                float w11 = (m1.y + 1e-6f) * __expf(sc[p][3]);
                rs0 += w00 + w01;
                rs1 += w10 + w11;
                wh[2*p]   = pack_h2(w00, w01);
                wh[2*p+1] = pack_h2(w10, w11);
            }
            // ---- PV via trans-ldmatrix straight from K tile ----
            #pragma unroll
            for (int ip = 0; ip < 2; ip++) {
                u32 vr[4];
                ldx4t(vr, ks + (u32)(((16*j + ((lane>>3)&1)*8 + (lane & 7))*40
                                      + ((lane>>4)&1)*8 + ip*16) * 2));
                mma_h(oacc[2*ip],   wh, vr[0], vr[1]);
                mma_h(oacc[2*ip+1], wh, vr[2], vr[3]);
            }
        }

        if (more) stK((kt + 1) & 1, n0v, n1v);
        __syncthreads();
    }

    rs0 += __shfl_xor_sync(0xffffffffu, rs0, 1);
    rs0 += __shfl_xor_sync(0xffffffffu, rs0, 2);
    rs1 += __shfl_xor_sync(0xffffffffu, rs1, 1);
    rs1 += __shfl_xor_sync(0xffffffffu, rs1, 2);
    float inv0 = 1.0f / rs0;
    float inv1 = 1.0f / rs1;

    if (r0 < SS) {
        float* o = d_acc + ((size_t)b*SS + r0)*CC + h*HD + 2*t4;
        #pragma unroll
        for (int i = 0; i < 4; i++)
            *(float2*)(o + i*8) = make_float2(oacc[i][0]*inv0, oacc[i][1]*inv0);
    }
    if (r1i < SS) {
        float* o = d_acc + ((size_t)b*SS + r1i)*CC + h*HD + 2*t4;
        #pragma unroll
        for (int i = 0; i < 4; i++)
            *(float2*)(o + i*8) = make_float2(oacc[i][2]*inv1, oacc[i][3]*inv1);
    }
}

// ---------------------------------------------------------------------------
// Kernel 3: LEPE depthwise 5x5 conv + acc split to fp16 hi/lo.
// ---------------------------------------------------------------------------
__global__ __launch_bounds__(256) void lepe_kernel(
    const float* __restrict__ lw, const float* __restrict__ lb)
{
    int blk = blockIdx.x;
    int b = blk / SS, srow = blk % SS;
    int c = threadIdx.x;
    size_t idx = ((size_t)b*SS + srow)*CC + c;
    float a = d_acc[idx];
    if (srow >= QN) {
        int p = srow - QN;
        int y = p / 56, x = p % 56;
        float l = lb[c];
        #pragma unroll
        for (int ky = 0; ky < 5; ky++) {
            int iy = y + ky - 2;
            if (iy < 0 || iy >= 56) continue;
            #pragma unroll
            for (int kx = 0; kx < 5; kx++) {
                int ix = x + kx - 2;
                if (ix < 0 || ix >= 56) continue;
                l += d_v[((size_t)b*SS + QN + iy*56 + ix)*CC + c] * lw[(ky*5 + kx)*CC + c];
            }
        }
        a += l;
    }
    __half h, lo; split_h(a, h, lo);
    d_acch[idx] = h;
    d_accl[idx] = lo;
}

// ---------------------------------------------------------------------------
// Kernel 4: output projection, split-fp16 HMMA (3-pass). 64x64 tiles.
// ---------------------------------------------------------------------------
__global__ __launch_bounds__(256) void out_kernel(
    const float* __restrict__ bo, float* __restrict__ out)
{
    __shared__ __align__(16) u16 Xh[64*40];
    __shared__ __align__(16) u16 Xl[64*40];
    __shared__ __align__(16) u16 Wh[64*40];
    __shared__ __align__(16) u16 Wl[64*40];

    const int m0 = blockIdx.x * 64;
    const int n0 = blockIdx.y * 64;
    const int t = threadIdx.x;
    const int w = t >> 5, lane = t & 31;
    const int g = lane >> 2, t4 = lane & 3;
    const int wr = w >> 1, wc = w & 1;

    float acc[4][4];
    #pragma unroll
    for (int i = 0; i < 4; i++)
        #pragma unroll
        for (int c = 0; c < 4; c++) acc[i][c] = 0.f;

    const u32 xb  = smem_u32(Xh), xlb = smem_u32(Xl);
    const u32 wb  = smem_u32(Wh), wlb = smem_u32(Wl);

    for (int kk = 0; kk < CC; kk += 32) {
        __syncthreads();
        {
            int r = t >> 2, c8 = (t & 3) * 8;
            int gm = m0 + r;
            uint4 a = make_uint4(0u,0u,0u,0u), bvv = make_uint4(0u,0u,0u,0u);
            if (gm < MTOT) {
                a   = *(const uint4*)&d_acch[(size_t)gm*CC + kk + c8];
                bvv = *(const uint4*)&d_accl[(size_t)gm*CC + kk + c8];
            }
            *(uint4*)&Xh[r*40 + c8] = a;
            *(uint4*)&Xl[r*40 + c8] = bvv;
            int wrow = n0 + r;
            *(uint4*)&Wh[r*40 + c8] = *(const uint4*)&d_woh[(size_t)wrow*CC + kk + c8];
            *(uint4*)&Wl[r*40 + c8] = *(const uint4*)&d_wol[(size_t)wrow*CC + kk + c8];
        }
        __syncthreads();

        u32 ax[2][4], al[2][4];
        #pragma unroll
        for (int ks = 0; ks < 2; ks++) {
            u32 aoff = (u32)(((16*wr + (lane & 15))*40 + ks*16 + ((lane>>4)&1)*8) * 2);
            ldx4(ax[ks], xb  + aoff);
            ldx4(al[ks], xlb + aoff);
        }
        #pragma unroll
        for (int ks = 0; ks < 2; ks++) {
            #pragma unroll
            for (int np = 0; np < 2; np++) {
                u32 boff = (u32)(((32*wc + np*16 + ((lane>>4)&1)*8 + (lane & 7))*40
                                  + ks*16 + ((lane>>3)&1)*8) * 2);
                u32 bh4[4], bl4[4];
                ldx4(bh4, wb  + boff);
                ldx4(bl4, wlb + boff);
                mma_h(acc[2*np],   ax[ks], bh4[0], bh4[1]);
                mma_h(acc[2*np],   ax[ks], bl4[0], bl4[1]);
                mma_h(acc[2*np],   al[ks], bh4[0], bh4[1]);
                mma_h(acc[2*np+1], ax[ks], bh4[2], bh4[3]);
                mma_h(acc[2*np+1], ax[ks], bl4[2], bl4[3]);
                mma_h(acc[2*np+1], al[ks], bh4[2], bh4[3]);
            }
        }
    }

    #pragma unroll
    for (int nt = 0; nt < 4; nt++) {
        int n = n0 + 32*wc + 8*nt + 2*t4;
        float b0v = bo[n], b1v = bo[n+1];
        #pragma unroll
        for (int rr = 0; rr < 2; rr++) {
            int gm = m0 + 16*wr + g + rr*8;
            if (gm >= MTOT) continue;
            *(float2*)&out[(size_t)gm*CC + n] =
                make_float2(acc[nt][2*rr] + b0v, acc[nt][2*rr+1] + b1v);
        }
    }
}

// ---------------------------------------------------------------------------
extern "C" void kernel_launch(void* const* d_in, const int* in_sizes, int n_in,
                              void* d_out, int out_size) {
    const float* x    = (const float*)d_in[0];
    const float* mask = (const float*)d_in[1];
    const float* wq   = (const float*)d_in[2];
    const float* bq   = (const float*)d_in[3];
    const float* wk   = (const float*)d_in[4];
    const float* bk   = (const float*)d_in[5];
    const float* wv   = (const float*)d_in[6];
    const float* bv   = (const float*)d_in[7];
    const float* lw   = (const float*)d_in[8];
    const float* lb   = (const float*)d_in[9];
    const float* wo   = (const float*)d_in[10];
    const float* bo   = (const float*)d_in[11];
    float* out = (float*)d_out;

    cvt_kernel<<<1024, 256>>>(wq, wk, wv, wo);
    dim3 g1(99, 12);
    qkv_kernel<<<g1, 256>>>(x, bq, bk, bv);
    dim3 g2(BB*4, NQT64);
    attn_mma_kernel<<<g2, 256>>>(mask);
    lepe_kernel<<<BB*SS, 256>>>(lw, lb);
    dim3 g4(99, 4);
    out_kernel<<<g4, 256>>>(bo, out);
}